// round 13
// baseline (speedup 1.0000x reference)
#include <cuda_runtime.h>
#include <math.h>
#include <stdint.h>

typedef signed char s8;

#define LL 12
#define DD 1024
#define HH 16
#define VV 50257
#define TT 256
#define BB 2
#define SS 768
#define HDIM 64
#define NR (BB * SS)

#define QS 68

// ---------------------------------------------------------------------------
// Device-global scratch
// ---------------------------------------------------------------------------
__device__ __align__(16) float g_x[NR * DD];
__device__ __align__(16) float g_qkv[NR * 3 * DD];
__device__ __align__(16) float g_y[NR * DD];
__device__ __align__(16) float g_ff[NR * 4 * DD];
__device__ __align__(16) float g_part[4 * NR * DD];

__device__ __align__(16) s8 g_hq_h[NR * DD], g_hq_l[NR * DD];
__device__ __align__(16) s8 g_yq_h[NR * DD], g_yq_l[NR * DD];
__device__ __align__(16) s8 g_fq_h[NR * 4 * DD], g_fq_l[NR * 4 * DD];
__device__ float g_s_h[NR], g_s_y[NR], g_s_f[NR];

#define SZ_QKV (LL * 3072 * 1024)
#define SZ_PROJ (LL * 1024 * 1024)
#define SZ_FC  (LL * 4096 * 1024)
#define SZ_FCP (LL * 1024 * 4096)
#define SZ_LM  (VV * 1024)
__device__ __align__(16) s8 wq_qh[SZ_QKV], wq_ql[SZ_QKV];
__device__ __align__(16) s8 wp_qh[SZ_PROJ], wp_ql[SZ_PROJ];
__device__ __align__(16) s8 wf_qh[SZ_FC],  wf_ql[SZ_FC];
__device__ __align__(16) s8 wg_qh[SZ_FCP], wg_ql[SZ_FCP];
__device__ __align__(16) s8 wl_qh[SZ_LM],  wl_ql[SZ_LM];
__device__ float sw_q[LL * 3072], sw_p[LL * 1024], sw_f[LL * 4096],
                 sw_g[LL * 1024], sw_lm[VV];

// ---------------------------------------------------------------------------
// helpers
// ---------------------------------------------------------------------------
__device__ __forceinline__ uint32_t smem_u32(const void* p) {
    uint32_t a;
    asm("{ .reg .u64 t; cvta.to.shared.u64 t, %1; cvt.u32.u64 %0, t; }"
        : "=r"(a) : "l"(p));
    return a;
}
__device__ __forceinline__ float fast_gelu(float x) {
    float u = 0.7978845608028654f * (x + 0.044715f * x * x * x);
    float th = 1.f - 2.f / (__expf(2.f * u) + 1.f);
    return 0.5f * x * (1.f + th);
}
__device__ __forceinline__ void quant2(float q, s8& qh, s8& ql) {
    float h = rintf(q);
    qh = (s8)(int)h;
    ql = (s8)(int)rintf((q - h) * 128.f);
}

#define CP_A16(dst, src) \
    asm volatile("cp.async.cg.shared.global [%0], [%1], 16;" \
                 :: "r"(dst), "l"(src))
#define CP_A16Z(dst, src, sz) \
    asm volatile("cp.async.cg.shared.global [%0], [%1], 16, %2;" \
                 :: "r"(dst), "l"(src), "r"(sz))
#define CP_COMMIT() asm volatile("cp.async.commit_group;")
#define CP_WAIT(n)  asm volatile("cp.async.wait_group %0;" :: "n"(n))

__device__ __forceinline__ void ldsm_x4(uint32_t* r, uint32_t addr) {
    asm volatile("ldmatrix.sync.aligned.m8n8.x4.shared.b16 {%0,%1,%2,%3}, [%4];"
                 : "=r"(r[0]), "=r"(r[1]), "=r"(r[2]), "=r"(r[3]) : "r"(addr));
}
#define MMA_I8(c, a, b0, b1) \
    asm volatile("mma.sync.aligned.m16n8k32.row.col.s32.s8.s8.s32 " \
                 "{%0,%1,%2,%3}, {%4,%5,%6,%7}, {%8,%9}, {%0,%1,%2,%3};" \
                 : "+r"((c)[0]), "+r"((c)[1]), "+r"((c)[2]), "+r"((c)[3]) \
                 : "r"((a)[0]), "r"((a)[1]), "r"((a)[2]), "r"((a)[3]), \
                   "r"(b0), "r"(b1))

// ---------------------------------------------------------------------------
// Weight quantization: per-N-row max, then transpose+quantize
// W[K,N] f32 -> qh/ql [N,K] int8, S[n] = rowmax/127
// ---------------------------------------------------------------------------
__global__ void wmax(const float* __restrict__ W, float* __restrict__ S,
                     int K, int N) {
    __shared__ float red[8][32];
    const size_t lof = (size_t)blockIdx.z * K * N;
    const int n0 = blockIdx.x * 32;
    const int tx = threadIdx.x, ty = threadIdx.y;
    float m = 0.f;
    for (int k = ty; k < K; k += 8)
        m = fmaxf(m, fabsf(W[lof + (size_t)k * N + n0 + tx]));
    red[ty][tx] = m;
    __syncthreads();
    if (ty == 0) {
        float a = red[0][tx];
#pragma unroll
        for (int i = 1; i < 8; i++) a = fmaxf(a, red[i][tx]);
        S[(size_t)blockIdx.z * N + n0 + tx] = fmaxf(a, 1e-20f) / 127.f;
    }
}

__global__ void __launch_bounds__(256) wquant(const float* __restrict__ W,
                                              const float* __restrict__ S,
                                              s8* __restrict__ Th,
                                              s8* __restrict__ Tl,
                                              int K, int N) {
    __shared__ float tile[32][33];
    const size_t lof = (size_t)blockIdx.z * K * N;
    const int n0 = blockIdx.x * 32, k0 = blockIdx.y * 32;
    const int tx = threadIdx.x, ty = threadIdx.y;
#pragma unroll
    for (int i = 0; i < 4; i++)
        tile[ty + i * 8][tx] = W[lof + (size_t)(k0 + ty + i * 8) * N + n0 + tx];
    __syncthreads();
#pragma unroll
    for (int i = 0; i < 4; i++) {
        int n = n0 + ty + i * 8;
        float inv = 1.f / S[(size_t)blockIdx.z * N + n];
        float q = tile[tx][ty + i * 8] * inv;
        s8 qh, ql;
        quant2(q, qh, ql);
        size_t o = lof + (size_t)n * K + k0 + tx;
        Th[o] = qh;
        Tl[o] = ql;
    }
}

// lm_w [V,K]: per-row quantize in one kernel
__global__ void __launch_bounds__(256) lmq(const float* __restrict__ W,
                                           s8* __restrict__ Th,
                                           s8* __restrict__ Tl,
                                           float* __restrict__ S) {
    int r = blockIdx.x;
    const float* row = W + (size_t)r * DD;
    float v[4], m = 0.f;
#pragma unroll
    for (int i = 0; i < 4; i++) {
        v[i] = row[threadIdx.x + i * 256];
        m = fmaxf(m, fabsf(v[i]));
    }
#pragma unroll
    for (int o = 16; o; o >>= 1) m = fmaxf(m, __shfl_xor_sync(~0u, m, o));
    __shared__ float rm[8];
    int warp = threadIdx.x >> 5, lane = threadIdx.x & 31;
    if (!lane) rm[warp] = m;
    __syncthreads();
    if (threadIdx.x == 0) {
        float a = rm[0];
#pragma unroll
        for (int i = 1; i < 8; i++) a = fmaxf(a, rm[i]);
        rm[0] = fmaxf(a, 1e-20f) / 127.f;
    }
    __syncthreads();
    float su = rm[0];
    if (threadIdx.x == 0) S[r] = su;
    float inv = 1.f / su;
#pragma unroll
    for (int i = 0; i < 4; i++) {
        s8 qh, ql;
        quant2(v[i] * inv, qh, ql);
        size_t o = (size_t)r * DD + threadIdx.x + i * 256;
        Th[o] = qh;
        Tl[o] = ql;
    }
}

// Activation quantize: per-row, re-reads (L2 hot)
__global__ void __launch_bounds__(256) actquant(const float* __restrict__ src,
                                                s8* __restrict__ qh_,
                                                s8* __restrict__ ql_,
                                                float* __restrict__ S, int N) {
    int r = blockIdx.x;
    const float* row = src + (size_t)r * N;
    float m = 0.f;
    for (int i = threadIdx.x; i < N; i += 256) m = fmaxf(m, fabsf(row[i]));
#pragma unroll
    for (int o = 16; o; o >>= 1) m = fmaxf(m, __shfl_xor_sync(~0u, m, o));
    __shared__ float rm[8];
    int warp = threadIdx.x >> 5, lane = threadIdx.x & 31;
    if (!lane) rm[warp] = m;
    __syncthreads();
    if (threadIdx.x == 0) {
        float a = rm[0];
#pragma unroll
        for (int i = 1; i < 8; i++) a = fmaxf(a, rm[i]);
        rm[0] = fmaxf(a, 1e-20f) / 127.f;
    }
    __syncthreads();
    float su = rm[0];
    if (threadIdx.x == 0) S[r] = su;
    float inv = 1.f / su;
    for (int i = threadIdx.x; i < N; i += 256) {
        s8 qh, ql;
        quant2(row[i] * inv, qh, ql);
        qh_[(size_t)r * N + i] = qh;
        ql_[(size_t)r * N + i] = ql;
    }
}

// ---------------------------------------------------------------------------
// combine4: x += p0..p3 + bias (last layer)
// ---------------------------------------------------------------------------
__global__ void __launch_bounds__(256) combine4(const float4* __restrict__ p,
                                                const float* __restrict__ bias,
                                                float4* __restrict__ x, int total4) {
    int i = blockIdx.x * 256 + threadIdx.x;
    if (i < total4) {
        float4 a = p[i], b = p[i + total4];
        float4 c2 = p[i + 2 * total4], d2 = p[i + 3 * total4];
        float4 c = x[i];
        int col = (i & (DD / 4 - 1)) * 4;
        c.x += a.x + b.x + c2.x + d2.x + bias[col];
        c.y += a.y + b.y + c2.y + d2.y + bias[col + 1];
        c.z += a.z + b.z + c2.z + d2.z + bias[col + 2];
        c.w += a.w + b.w + c2.w + d2.w + bias[col + 3];
        x[i] = c;
    }
}

// ---------------------------------------------------------------------------
// LN body shared logic: normalize then int8-quantize a row
// ---------------------------------------------------------------------------
__device__ __forceinline__ void ln_quant_row(
    float v0, float v1, float v2, float v3,
    const float* w, const float* b, int row,
    s8* oh, s8* ol, float* S)
{
    float v[4] = {v0, v1, v2, v3};
    float s = v[0] + v[1] + v[2] + v[3];
    float s2 = v[0]*v[0] + v[1]*v[1] + v[2]*v[2] + v[3]*v[3];
#pragma unroll
    for (int o = 16; o; o >>= 1) {
        s  += __shfl_xor_sync(~0u, s,  o);
        s2 += __shfl_xor_sync(~0u, s2, o);
    }
    __shared__ float rs[8], rs2[8], rmax[8];
    int warp = threadIdx.x >> 5, lane = threadIdx.x & 31;
    if (!lane) { rs[warp] = s; rs2[warp] = s2; }
    __syncthreads();
    if (threadIdx.x == 0) {
        float a = 0.f, a2 = 0.f;
#pragma unroll
        for (int i = 0; i < 8; i++) { a += rs[i]; a2 += rs2[i]; }
        rs[0] = a; rs2[0] = a2;
    }
    __syncthreads();
    float mean = rs[0] * (1.f / DD);
    float var  = rs2[0] * (1.f / DD) - mean * mean;
    float inv  = rsqrtf(var + 1e-5f);
    float t[4], mx = 0.f;
#pragma unroll
    for (int i = 0; i < 4; i++) {
        int d = threadIdx.x + i * 256;
        t[i] = (v[i] - mean) * inv * w[d] + b[d];
        mx = fmaxf(mx, fabsf(t[i]));
    }
#pragma unroll
    for (int o = 16; o; o >>= 1) mx = fmaxf(mx, __shfl_xor_sync(~0u, mx, o));
    if (!lane) rmax[warp] = mx;
    __syncthreads();
    if (threadIdx.x == 0) {
        float a = rmax[0];
#pragma unroll
        for (int i = 1; i < 8; i++) a = fmaxf(a, rmax[i]);
        rmax[0] = fmaxf(a, 1e-20f) / 127.f;
    }
    __syncthreads();
    float su = rmax[0];
    if (threadIdx.x == 0) S[row] = su;
    float qinv = 1.f / su;
#pragma unroll
    for (int i = 0; i < 4; i++) {
        int d = threadIdx.x + i * 256;
        s8 qh, ql;
        quant2(t[i] * qinv, qh, ql);
        oh[(size_t)row * DD + d] = qh;
        ol[(size_t)row * DD + d] = ql;
    }
}

__global__ void __launch_bounds__(256) ln_kernel(const float* __restrict__ x,
                                                 const float* __restrict__ w,
                                                 const float* __restrict__ b,
                                                 s8* oh, s8* ol, float* S) {
    int row = blockIdx.x;
    const float* xr = x + (size_t)row * DD;
    ln_quant_row(xr[threadIdx.x], xr[threadIdx.x + 256],
                 xr[threadIdx.x + 512], xr[threadIdx.x + 768],
                 w, b, row, oh, ol, S);
}

// combine + LN + quantize
__global__ void __launch_bounds__(256) combine_ln(
    const float* __restrict__ part, const float* __restrict__ cbias,
    const float* __restrict__ w, const float* __restrict__ b,
    float* __restrict__ x, s8* oh, s8* ol, float* S) {
    int row = blockIdx.x;
    const size_t TOT = (size_t)NR * DD;
    float v[4];
#pragma unroll
    for (int i = 0; i < 4; i++) {
        int d = threadIdx.x + i * 256;
        size_t o = (size_t)row * DD + d;
        float val = x[o] + part[o] + part[TOT + o] + part[2 * TOT + o]
                  + part[3 * TOT + o] + cbias[d];
        x[o] = val;
        v[i] = val;
    }
    ln_quant_row(v[0], v[1], v[2], v[3], w, b, row, oh, ol, S);
}

// Final LN with state-row gather: row m -> src b*S+3t+1, into g_hq rows 0..511
__global__ void __launch_bounds__(256) lnf_kernel(const float* __restrict__ w,
                                                  const float* __restrict__ b) {
    int m = blockIdx.x;
    int bb = m / TT, t = m % TT;
    int src = bb * SS + 3 * t + 1;
    const float* xr = g_x + (size_t)src * DD;
    ln_quant_row(xr[threadIdx.x], xr[threadIdx.x + 256],
                 xr[threadIdx.x + 512], xr[threadIdx.x + 768],
                 w, b, m, g_hq_h, g_hq_l, g_s_h);
}

// ---------------------------------------------------------------------------
// int8 GEMM: C[M,N] = diag(sa) (Qa + La/128)(Qw + Lw/128)^T diag(sw)
// BM=128, BN=64, BK=64, 8 warps (4M x 2N), warp tile 32x32, m16n8k32 IMMA.
// 3 passes: hi*hi -> accM; hi*lo + lo*hi -> accC (shared). Exact s32 accum.
// epi: 0 f32(+bias, N-guarded); 1 bias+GELU->f32; 3 raw partial f32
// smem: 2 stages x (A 2x128x80 + B 2x64x80) = 61440 B
// ---------------------------------------------------------------------------
#define ASZ (128 * 80)
#define BSZ (64 * 80)
#define STG (2 * ASZ + 2 * BSZ)   // 30720 B/stage

__global__ void __launch_bounds__(256, 2) gemm_i8(
    const s8* __restrict__ Ah, const s8* __restrict__ Al,
    const float* __restrict__ Sa,
    const s8* __restrict__ Wh, const s8* __restrict__ Wl,
    const float* __restrict__ Sw,
    const float* __restrict__ bias, float* __restrict__ Cf,
    int N, int K, int Kfull, int epi)
{
    extern __shared__ __align__(16) s8 smem_g[];
    const uint32_t sbase = smem_u32(smem_g);

    const int tid = threadIdx.x;
    const int m0 = blockIdx.y * 128, n0 = blockIdx.x * 64;
    const int koff = blockIdx.z * K;
    if (epi == 3)
        Cf += (size_t)blockIdx.z * ((size_t)gridDim.y * 128) * N;
    const int lane = tid & 31, w = tid >> 5;
    const int wm = (w & 3) * 32, wn = (w >> 2) * 32;
    const int lr = lane >> 2;
    const int lc = (lane & 3) * 2;

    const int rowA_l = wm + ((lane >> 3) & 1) * 8 + (lane & 7);
    const int kA_b   = ((lane >> 4) & 1) * 16;
    const int rowB_l = wn + (lane & 7) + ((lane >> 4) & 1) * 8;
    const int kB_b   = ((lane >> 3) & 1) * 16;

    int accM[2][4][4], accC[2][4][4];
#pragma unroll
    for (int i = 0; i < 2; i++)
#pragma unroll
        for (int j = 0; j < 4; j++)
#pragma unroll
            for (int q = 0; q < 4; q++) { accM[i][j][q] = 0; accC[i][j][q] = 0; }

    const int nch = K >> 6;
    const int arow = tid >> 1, acb = tid & 1;     // A: 2 slots/thread via it
    const int brow = tid >> 2, bcb = tid & 3;     // B: 1 slot/thread

    auto stage = [&](int kc, int st) {
        const int kb = koff + (kc << 6);
        const uint32_t base = sbase + (uint32_t)st * STG;
#pragma unroll
        for (int it = 0; it < 2; it++) {
            int ac = acb + it * 2;
            size_t ga = (size_t)(m0 + arow) * Kfull + kb + ac * 16;
            uint32_t da = base + (uint32_t)(arow * 80 + ac * 16);
            CP_A16(da,       &Ah[ga]);
            CP_A16(da + ASZ, &Al[ga]);
        }
        {
            int n = n0 + brow;
            int ok = (n < N);
            size_t gb = (size_t)(ok ? n : 0) * Kfull + kb + bcb * 16;
            uint32_t sz = ok ? 16u : 0u;
            uint32_t db = base + 2 * ASZ + (uint32_t)(brow * 80 + bcb * 16);
            CP_A16Z(db,       &Wh[gb], sz);
            CP_A16Z(db + BSZ, &Wl[gb], sz);
        }
    };

    stage(0, 0);
    CP_COMMIT();

    for (int kc = 0; kc < nch; kc++) {
        const int st = kc & 1;
        if (kc + 1 < nch) {
            stage(kc + 1, st ^ 1);
            CP_COMMIT();
            CP_WAIT(1);
        } else {
            CP_WAIT(0);
        }
        __syncthreads();

        const uint32_t bA  = sbase + (uint32_t)st * STG;
        const uint32_t bAl = bA + ASZ;
        const uint32_t bB  = bA + 2 * ASZ;
        const uint32_t bBl = bB + BSZ;

#pragma unroll
        for (int ks = 0; ks < 2; ks++) {
            const int kof = ks * 32;
            uint32_t bh[2][4], bl[2][4];
#pragma unroll
            for (int jj = 0; jj < 2; jj++) {
                uint32_t aB = (uint32_t)((rowB_l + jj * 16) * 80 + kB_b + kof);
                ldsm_x4(bh[jj], bB + aB);
                ldsm_x4(bl[jj], bBl + aB);
            }
#pragma unroll
            for (int i = 0; i < 2; i++) {
                uint32_t ah[4], al[4];
                uint32_t aA = (uint32_t)((rowA_l + i * 16) * 80 + kA_b + kof);
                ldsm_x4(ah, bA + aA);
                ldsm_x4(al, bAl + aA);
#pragma unroll
                for (int jj = 0; jj < 2; jj++) {
                    MMA_I8(accM[i][jj * 2],     ah, bh[jj][0], bh[jj][1]);
                    MMA_I8(accM[i][jj * 2 + 1], ah, bh[jj][2], bh[jj][3]);
                    MMA_I8(accC[i][jj * 2],     ah, bl[jj][0], bl[jj][1]);
                    MMA_I8(accC[i][jj * 2 + 1], ah, bl[jj][2], bl[jj][3]);
                    MMA_I8(accC[i][jj * 2],     al, bh[jj][0], bh[jj][1]);
                    MMA_I8(accC[i][jj * 2 + 1], al, bh[jj][2], bh[jj][3]);
                }
            }
        }
        __syncthreads();
    }

    // ---- epilogue: C = sa*sw*(accM + accC/128) ----
    float sar[2][2];
#pragma unroll
    for (int i = 0; i < 2; i++) {
        sar[i][0] = Sa[m0 + wm + i * 16 + lr];
        sar[i][1] = Sa[m0 + wm + i * 16 + lr + 8];
    }
#pragma unroll
    for (int i = 0; i < 2; i++)
#pragma unroll
        for (int j = 0; j < 4; j++) {
            int col = n0 + wn + j * 8 + lc;
            float sw0 = (col < N)     ? Sw[col]     : 0.f;
            float sw1 = (col + 1 < N) ? Sw[col + 1] : 0.f;
#pragma unroll
            for (int half = 0; half < 2; half++) {
                int row = m0 + wm + i * 16 + lr + half * 8;
                float base0 = (float)accM[i][j][half * 2 + 0]
                            + 0.0078125f * (float)accC[i][j][half * 2 + 0];
                float base1 = (float)accM[i][j][half * 2 + 1]
                            + 0.0078125f * (float)accC[i][j][half * 2 + 1];
                float v0 = sar[i][half] * sw0 * base0;
                float v1 = sar[i][half] * sw1 * base1;
                size_t o = (size_t)row * N + col;
                if (epi == 1) {
                    Cf[o]     = fast_gelu(v0 + bias[col]);
                    Cf[o + 1] = fast_gelu(v1 + bias[col + 1]);
                } else if (epi == 3) {
                    Cf[o] = v0;
                    Cf[o + 1] = v1;
                } else {
                    if (bias) {
                        v0 += (col < N) ? bias[col] : 0.f;
                        v1 += (col + 1 < N) ? bias[col + 1] : 0.f;
                    }
                    if (col < N) Cf[o] = v0;
                    if (col + 1 < N) Cf[o + 1] = v1;
                }
            }
        }
}

// ---------------------------------------------------------------------------
// Embedding
// ---------------------------------------------------------------------------
__global__ void embed_kernel(const float* __restrict__ states,
                             const int* __restrict__ actions,
                             const float* __restrict__ rtgs,
                             const int* __restrict__ tsteps,
                             const float* __restrict__ se_w, const float* __restrict__ se_b,
                             const float* __restrict__ re_w, const float* __restrict__ re_b,
                             const float* __restrict__ ae,
                             const float* __restrict__ pe,
                             const float* __restrict__ gpe) {
    int s = blockIdx.x;
    int b = blockIdx.y;
    int t = s / 3, kind = s % 3;
    int ts = tsteps[b];
    const float* g = gpe + (size_t)ts * DD;
    const float* p = pe + (size_t)s * DD;
    float* out = g_x + ((size_t)(b * SS + s)) * DD;

    if (kind == 0) {
        float r = rtgs[b * TT + t];
        for (int d = threadIdx.x; d < DD; d += blockDim.x)
            out[d] = fmaf(r, re_w[d], re_b[d]) + g[d] + p[d];
    } else if (kind == 1) {
        float st = states[b * TT + t];
        for (int d = threadIdx.x; d < DD; d += blockDim.x)
            out[d] = fmaf(st, se_w[d], se_b[d]) + g[d] + p[d];
    } else {
        int a = actions[b * TT + t];
        const float* av = ae + (size_t)a * DD;
        for (int d = threadIdx.x; d < DD; d += blockDim.x)
            out[d] = av[d] + g[d] + p[d];
    }
}

// ---------------------------------------------------------------------------
// Flash attention (f32 compute, f32 output to g_y)
// ---------------------------------------------------------------------------
__global__ void __launch_bounds__(128) attn_flash() {
    extern __shared__ float sm[];
    float* Qs = sm;
    float* Ks = sm + 64 * QS;
    float* Ps = sm + 2 * 64 * QS;
    float* Vs = sm + 3 * 64 * QS;

    const int qt = blockIdx.x, h = blockIdx.y, b = blockIdx.z;
    const float* base = g_qkv + (size_t)b * SS * (3 * DD);
    const int tid = threadIdx.x;
    const int tq = tid >> 3, tk = tid & 7;

    for (int i = tid; i < 1024; i += 128) {
        int r = i >> 4, dg = i & 15;
        float4 v = *reinterpret_cast<const float4*>(
            &base[(size_t)(qt * 64 + r) * (3 * DD) + h * HDIM + dg * 4]);
        Qs[(dg * 4 + 0) * QS + r] = v.x;
        Qs[(dg * 4 + 1) * QS + r] = v.y;
        Qs[(dg * 4 + 2) * QS + r] = v.z;
        Qs[(dg * 4 + 3) * QS + r] = v.w;
    }

    float m_i[4], l_i[4], O[4][8];
#pragma unroll
    for (int i = 0; i < 4; i++) {
        m_i[i] = -1e30f; l_i[i] = 0.f;
#pragma unroll
        for (int j = 0; j < 8; j++) O[i][j] = 0.f;
    }

    for (int kt = 0; kt <= qt; kt++) {
        __syncthreads();
        for (int i = tid; i < 1024; i += 128) {
            int r = i >> 4, dg = i & 15;
            const float* krow = &base[(size_t)(kt * 64 + r) * (3 * DD) + DD + h * HDIM];
            float4 kv = *reinterpret_cast<const float4*>(krow + dg * 4);
            Ks[(dg * 4 + 0) * QS + r] = kv.x;
            Ks[(dg * 4 + 1) * QS + r] = kv.y;
            Ks[(dg * 4 + 2) * QS + r] = kv.z;
            Ks[(dg * 4 + 3) * QS + r] = kv.w;
            float4 vv = *reinterpret_cast<const float4*>(
                &base[(size_t)(kt * 64 + r) * (3 * DD) + 2 * DD + h * HDIM + dg * 4]);
            *reinterpret_cast<float4*>(&Vs[r * 64 + dg * 4]) = vv;
        }
        __syncthreads();

        float s[4][8];
#pragma unroll
        for (int i = 0; i < 4; i++)
#pragma unroll
            for (int j = 0; j < 8; j++) s[i][j] = 0.f;
#pragma unroll 8
        for (int d = 0; d < 64; d++) {
            float4 a = *reinterpret_cast<const float4*>(&Qs[d * QS + tq * 4]);
            float4 b0 = *reinterpret_cast<const float4*>(&Ks[d * QS + tk * 8]);
            float4 b1 = *reinterpret_cast<const float4*>(&Ks[d * QS + tk * 8 + 4]);
            float ar[4] = {a.x, a.y, a.z, a.w};
            float br[8] = {b0.x, b0.y, b0.z, b0.w, b1.x, b1.y, b1.z, b1.w};
#pragma unroll
            for (int i = 0; i < 4; i++)
#pragma unroll
                for (int j = 0; j < 8; j++)
                    s[i][j] = fmaf(ar[i], br[j], s[i][j]);
        }
        const bool diag = (kt == qt);
#pragma unroll
        for (int i = 0; i < 4; i++) {
            int qg = qt * 64 + tq * 4 + i;
#pragma unroll
            for (int j = 0; j < 8; j++) {
                int kg = kt * 64 + tk * 8 + j;
                s[i][j] = (diag && kg > qg) ? -1e30f : s[i][j] * 0.125f;
            }
        }
        float e[4][8];
#pragma unroll
        for (int i = 0; i < 4; i++) {
            float rm = s[i][0];
#pragma unroll
            for (int j = 1; j < 8; j++) rm = fmaxf(rm, s[i][j]);
            rm = fmaxf(rm, __shfl_xor_sync(~0u, rm, 1));
            rm = fmaxf(rm, __shfl_xor_sync(~0u, rm, 2));
            rm = fmaxf(rm, __shfl_xor_sync(~0u, rm, 4));
            float newm = fmaxf(m_i[i], rm);
            float f = __expf(m_i[i] - newm);
            float es = 0.f;
#pragma unroll
            for (int j = 0; j < 8; j++) {
                float ev = __expf(s[i][j] - newm);
                e[i][j] = ev; es += ev;
            }
            es += __shfl_xor_sync(~0u, es, 1);
            es += __shfl_xor_sync(~0u, es, 2);
            es += __shfl_xor_sync(~0u, es, 4);
            l_i[i] = l_i[i] * f + es;
            m_i[i] = newm;
#pragma unroll
            for (int j = 0; j < 8; j++) O[i][j] *= f;
        }
#pragma unroll
        for (int j = 0; j < 8; j++)
#pragma unroll
            for (int i = 0; i < 4; i++)
                Ps[(tk * 8 + j) * QS + tq * 4 + i] = e[i][j];
        __syncthreads();
#pragma unroll 8
        for (int k = 0; k < 64; k++) {
            float4 a = *reinterpret_cast<const float4*>(&Ps[k * QS + tq * 4]);
            float4 b0 = *reinterpret_cast<const float4*>(&Vs[k * 64 + tk * 8]);
            float4 b1 = *reinterpret_cast<const float4*>(&Vs[k * 64 + tk * 8 + 4]);
            float ar[4] = {a.x, a.y, a.z, a.w};
            float br[8] = {b0.x, b0.y, b0.z, b0.w, b1.x, b1.y, b1.z, b1.w};
#pragma unroll
            for (int i = 0; i < 4; i++)
#pragma unroll
                for (int j = 0; j < 8; j++)
                    O[i][j] = fmaf(ar[i], br[j], O[i][j]);
        }
    }

#pragma unroll
    for (int i = 0; i < 4; i++) {
        float inv = 1.f / l_i[i];
        int q = qt * 64 + tq * 4 + i;
        float* orow = &g_y[((size_t)(b * SS + q)) * DD + h * HDIM + tk * 8];
        float4 o0 = make_float4(O[i][0]*inv, O[i][1]*inv, O[i][2]*inv, O[i][3]*inv);
        float4 o1 = make_float4(O[i][4]*inv, O[i][5]*inv, O[i][6]*inv, O[i][7]*inv);
        *reinterpret_cast<float4*>(orow) = o0;
        *reinterpret_cast<float4*>(orow + 4) = o1;
    }
}

// ---------------------------------------------------------------------------
// Launcher
// ---------------------------------------------------------------------------
extern "C" void kernel_launch(void* const* d_in, const int* in_sizes, int n_in,
                              void* d_out, int out_size) {
    const float* states  = (const float*)d_in[0];
    const int*   actions = (const int*)  d_in[1];
    const float* rtgs    = (const float*)d_in[2];
    const int*   tsteps  = (const int*)  d_in[3];
    const float* se_w = (const float*)d_in[4],  *se_b = (const float*)d_in[5];
    const float* re_w = (const float*)d_in[6],  *re_b = (const float*)d_in[7];
    const float* ae   = (const float*)d_in[8];
    const float* pe   = (const float*)d_in[9];
    const float* gpe  = (const float*)d_in[10];
    const float* ln1_w = (const float*)d_in[11], *ln1_b = (const float*)d_in[12];
    const float* qkv_w = (const float*)d_in[13], *qkv_b = (const float*)d_in[14];
    const float* proj_w= (const float*)d_in[15], *proj_b= (const float*)d_in[16];
    const float* ln2_w = (const float*)d_in[17], *ln2_b = (const float*)d_in[18];
    const float* fc_w  = (const float*)d_in[19], *fc_b  = (const float*)d_in[20];
    const float* fcp_w = (const float*)d_in[21], *fcp_b = (const float*)d_in[22];
    const float* lnf_w = (const float*)d_in[23], *lnf_b = (const float*)d_in[24];
    const float* lm_w  = (const float*)d_in[25];
    float* out = (float*)d_out;

    float *x, *qkv, *y, *ff, *part;
    float *sh, *sy, *sf, *swq, *swp, *swf, *swg, *swl;
    s8 *hqh, *hql, *yqh, *yql, *fqh, *fql;
    s8 *wqh, *wql, *wph, *wpl, *wfh, *wfl, *wgh, *wgl, *wlh, *wll;
    cudaGetSymbolAddress((void**)&x,    g_x);
    cudaGetSymbolAddress((void**)&qkv,  g_qkv);
    cudaGetSymbolAddress((void**)&y,    g_y);
    cudaGetSymbolAddress((void**)&ff,   g_ff);
    cudaGetSymbolAddress((void**)&part, g_part);
    cudaGetSymbolAddress((void**)&hqh,  g_hq_h);
    cudaGetSymbolAddress((void**)&hql,  g_hq_l);
    cudaGetSymbolAddress((void**)&yqh,  g_yq_h);
    cudaGetSymbolAddress((void**)&yql,  g_yq_l);
    cudaGetSymbolAddress((void**)&fqh,  g_fq_h);
    cudaGetSymbolAddress((void**)&fql,  g_fq_l);
    cudaGetSymbolAddress((void**)&sh,   g_s_h);
    cudaGetSymbolAddress((void**)&sy,   g_s_y);
    cudaGetSymbolAddress((void**)&sf,   g_s_f);
    cudaGetSymbolAddress((void**)&wqh,  wq_qh);
    cudaGetSymbolAddress((void**)&wql,  wq_ql);
    cudaGetSymbolAddress((void**)&wph,  wp_qh);
    cudaGetSymbolAddress((void**)&wpl,  wp_ql);
    cudaGetSymbolAddress((void**)&wfh,  wf_qh);
    cudaGetSymbolAddress((void**)&wfl,  wf_ql);
    cudaGetSymbolAddress((void**)&wgh,  wg_qh);
    cudaGetSymbolAddress((void**)&wgl,  wg_ql);
    cudaGetSymbolAddress((void**)&wlh,  wl_qh);
    cudaGetSymbolAddress((void**)&wll,  wl_ql);
    cudaGetSymbolAddress((void**)&swq,  sw_q);
    cudaGetSymbolAddress((void**)&swp,  sw_p);
    cudaGetSymbolAddress((void**)&swf,  sw_f);
    cudaGetSymbolAddress((void**)&swg,  sw_g);
    cudaGetSymbolAddress((void**)&swl,  sw_lm);

    const int SMEM_ATTN = (3 * 64 * QS + 64 * 64) * 4;   // 68608
    const int SMEM_GEMM = 2 * STG;                        // 61440
    cudaFuncSetAttribute(attn_flash,
                         cudaFuncAttributeMaxDynamicSharedMemorySize, SMEM_ATTN);
    cudaFuncSetAttribute(gemm_i8,
                         cudaFuncAttributeMaxDynamicSharedMemorySize, SMEM_GEMM);

    const int total4 = NR * DD / 4;
    const int cgrid = (total4 + 255) / 256;

    // weight quantization
    wmax<<<dim3(3072 / 32, 1, LL), dim3(32, 8)>>>(qkv_w, swq, 1024, 3072);
    wquant<<<dim3(3072 / 32, 1024 / 32, LL), dim3(32, 8)>>>(qkv_w, swq, wqh, wql, 1024, 3072);
    wmax<<<dim3(1024 / 32, 1, LL), dim3(32, 8)>>>(proj_w, swp, 1024, 1024);
    wquant<<<dim3(1024 / 32, 1024 / 32, LL), dim3(32, 8)>>>(proj_w, swp, wph, wpl, 1024, 1024);
    wmax<<<dim3(4096 / 32, 1, LL), dim3(32, 8)>>>(fc_w, swf, 1024, 4096);
    wquant<<<dim3(4096 / 32, 1024 / 32, LL), dim3(32, 8)>>>(fc_w, swf, wfh, wfl, 1024, 4096);
    wmax<<<dim3(1024 / 32, 1, LL), dim3(32, 8)>>>(fcp_w, swg, 4096, 1024);
    wquant<<<dim3(1024 / 32, 4096 / 32, LL), dim3(32, 8)>>>(fcp_w, swg, wgh, wgl, 4096, 1024);
    lmq<<<VV, 256>>>(lm_w, wlh, wll, swl);

    embed_kernel<<<dim3(SS, BB), 256>>>(states, actions, rtgs, tsteps,
                                        se_w, se_b, re_w, re_b, ae, pe, gpe);
    ln_kernel<<<NR, 256>>>(x, ln1_w, ln1_b, hqh, hql, sh);

    for (int l = 0; l < LL; l++) {
        gemm_i8<<<dim3(3072 / 64, NR / 128), 256, SMEM_GEMM>>>(
            hqh, hql, sh, wqh + (size_t)l * 3072 * 1024, wql + (size_t)l * 3072 * 1024,
            swq + (size_t)l * 3072, qkv_b + (size_t)l * 3072, qkv,
            3072, 1024, 1024, 0);
        attn_flash<<<dim3(SS / 64, HH, BB), 128, SMEM_ATTN>>>();
        actquant<<<NR, 256>>>(y, yqh, yql, sy, 1024);
        gemm_i8<<<dim3(1024 / 64, NR / 128, 4), 256, SMEM_GEMM>>>(
            yqh, yql, sy, wph + (size_t)l * 1024 * 1024, wpl + (size_t)l * 1024 * 1024,
            swp + (size_t)l * 1024, nullptr, part, 1024, 256, 1024, 3);
        combine_ln<<<NR, 256>>>(part, proj_b + (size_t)l * 1024,
                                ln2_w + l * DD, ln2_b + l * DD, x, hqh, hql, sh);
        gemm_i8<<<dim3(4096 / 64, NR / 128), 256, SMEM_GEMM>>>(
            hqh, hql, sh, wfh + (size_t)l * 4096 * 1024, wfl + (size_t)l * 4096 * 1024,
            swf + (size_t)l * 4096, fc_b + (size_t)l * 4096, ff,
            4096, 1024, 1024, 1);
        actquant<<<NR, 256>>>(ff, fqh, fql, sf, 4096);
        gemm_i8<<<dim3(1024 / 64, NR / 128, 4), 256, SMEM_GEMM>>>(
            fqh, fql, sf, wgh + (size_t)l * 1024 * 4096, wgl + (size_t)l * 1024 * 4096,
            swg + (size_t)l * 1024, nullptr, part, 1024, 1024, 4096, 3);
        if (l < LL - 1) {
            combine_ln<<<NR, 256>>>(part, fcp_b + (size_t)l * 1024,
                                    ln1_w + (l + 1) * DD, ln1_b + (l + 1) * DD,
                                    x, hqh, hql, sh);
        } else {
            combine4<<<cgrid, 256>>>((const float4*)part, fcp_b + (size_t)l * 1024,
                                     (float4*)x, total4);
            lnf_kernel<<<BB * TT, 256>>>(lnf_w, lnf_b);
        }
    }

    gemm_i8<<<dim3((VV + 63) / 64, (BB * TT) / 128), 256, SMEM_GEMM>>>(
        hqh, hql, sh, wlh, wll, swl, nullptr, out, VV, 1024, 1024, 0);
}

// round 14
// speedup vs baseline: 1.5262x; 1.5262x over previous
#include <cuda_runtime.h>
#include <cuda_fp16.h>
#include <math.h>
#include <stdint.h>

typedef unsigned short u16;

// Problem constants
#define LL 12
#define DD 1024
#define HH 16
#define VV 50257
#define TT 256
#define BB 2
#define SS 768
#define HDIM 64
#define NR (BB * SS)   // 1536 rows

#define QS 68   // attention smem row stride (floats)
#define LO_SCALE 2048.0f
#define LO_INV 4.8828125e-4f

// ---------------------------------------------------------------------------
// Device-global scratch
// ---------------------------------------------------------------------------
__device__ __align__(16) float g_x[NR * DD];
__device__ __align__(16) float g_qkv[NR * 3 * DD];
__device__ __align__(16) float g_part[4 * NR * DD];
__device__ __align__(16) u16 g_h_hi[NR * DD],  g_h_lo[NR * DD];
__device__ __align__(16) u16 g_y_hi[NR * DD],  g_y_lo[NR * DD];
__device__ __align__(16) u16 g_ff_hi[NR * 4 * DD], g_ff_lo[NR * 4 * DD];

#define SZ_QKV (LL * 3072 * 1024)
#define SZ_PROJ (LL * 1024 * 1024)
#define SZ_FC  (LL * 4096 * 1024)
#define SZ_FCP (LL * 1024 * 4096)
#define SZ_LM  (VV * 1024)
__device__ __align__(16) u16 w_qkv_h[SZ_QKV], w_qkv_l[SZ_QKV];
__device__ __align__(16) u16 w_proj_h[SZ_PROJ], w_proj_l[SZ_PROJ];
__device__ __align__(16) u16 w_fc_h[SZ_FC],   w_fc_l[SZ_FC];
__device__ __align__(16) u16 w_fcp_h[SZ_FCP], w_fcp_l[SZ_FCP];
__device__ __align__(16) u16 w_lm_h[SZ_LM],   w_lm_l[SZ_LM];

// ---------------------------------------------------------------------------
// helpers: fp16 split, lo scaled by 2^11
// ---------------------------------------------------------------------------
__device__ __forceinline__ void splitf(float v, u16& hi, u16& lo) {
    __half h = __float2half_rn(v);
    float r = (v - __half2float(h)) * LO_SCALE;
    hi = __half_as_ushort(h);
    lo = __half_as_ushort(__float2half_rn(r));
}
__device__ __forceinline__ uint32_t smem_u32(const void* p) {
    uint32_t a;
    asm("{ .reg .u64 t; cvta.to.shared.u64 t, %1; cvt.u32.u64 %0, t; }"
        : "=r"(a) : "l"(p));
    return a;
}
__device__ __forceinline__ float fast_gelu(float x) {
    float u = 0.7978845608028654f * (x + 0.044715f * x * x * x);
    float th = 1.f - 2.f / (__expf(2.f * u) + 1.f);
    return 0.5f * x * (1.f + th);
}

#define CP_A16(dst, src) \
    asm volatile("cp.async.cg.shared.global [%0], [%1], 16;" \
                 :: "r"(dst), "l"(src))
#define CP_A16Z(dst, src, sz) \
    asm volatile("cp.async.cg.shared.global [%0], [%1], 16, %2;" \
                 :: "r"(dst), "l"(src), "r"(sz))
#define CP_COMMIT() asm volatile("cp.async.commit_group;")
#define CP_WAIT(n)  asm volatile("cp.async.wait_group %0;" :: "n"(n))

__device__ __forceinline__ void ldsm_x4(uint32_t* r, uint32_t addr) {
    asm volatile("ldmatrix.sync.aligned.m8n8.x4.shared.b16 {%0,%1,%2,%3}, [%4];"
                 : "=r"(r[0]), "=r"(r[1]), "=r"(r[2]), "=r"(r[3]) : "r"(addr));
}
#define MMA_F32(c, a, b) \
    asm volatile("mma.sync.aligned.m16n8k16.row.col.f32.f16.f16.f32 " \
                 "{%0,%1,%2,%3}, {%4,%5,%6,%7}, {%8,%9}, {%0,%1,%2,%3};" \
                 : "+f"((c)[0]), "+f"((c)[1]), "+f"((c)[2]), "+f"((c)[3]) \
                 : "r"((a)[0]), "r"((a)[1]), "r"((a)[2]), "r"((a)[3]), \
                   "r"((b)[0]), "r"((b)[1]))
#define MMA_F16(c, a, b) \
    asm volatile("mma.sync.aligned.m16n8k16.row.col.f16.f16.f16.f16 " \
                 "{%0,%1}, {%2,%3,%4,%5}, {%6,%7}, {%0,%1};" \
                 : "+r"((c)[0]), "+r"((c)[1]) \
                 : "r"((a)[0]), "r"((a)[1]), "r"((a)[2]), "r"((a)[3]), \
                   "r"((b)[0]), "r"((b)[1]))

// ---------------------------------------------------------------------------
// Weight conversion: W[K,N] f32 -> T[N,K] fp16 hi/lo(x2048)
// ---------------------------------------------------------------------------
__global__ void __launch_bounds__(256) wconv(const float* __restrict__ W,
                                             u16* __restrict__ Th,
                                             u16* __restrict__ Tl,
                                             int K, int N) {
    __shared__ float tile[32][33];
    const size_t lof = (size_t)blockIdx.z * K * N;
    const float* Wp = W + lof;
    u16* Thp = Th + lof;
    u16* Tlp = Tl + lof;
    const int n0 = blockIdx.x * 32, k0 = blockIdx.y * 32;
    const int tx = threadIdx.x, ty = threadIdx.y;
#pragma unroll
    for (int i = 0; i < 4; i++)
        tile[ty + i * 8][tx] = Wp[(size_t)(k0 + ty + i * 8) * N + n0 + tx];
    __syncthreads();
#pragma unroll
    for (int i = 0; i < 4; i++) {
        float v = tile[tx][ty + i * 8];
        u16 hi, lo;
        splitf(v, hi, lo);
        size_t o = (size_t)(n0 + ty + i * 8) * K + k0 + tx;
        Thp[o] = hi;
        Tlp[o] = lo;
    }
}

__global__ void lmconv(const float* __restrict__ W, u16* __restrict__ Th,
                       u16* __restrict__ Tl, int total) {
    int i = blockIdx.x * 256 + threadIdx.x;
    if (i < total) {
        u16 hi, lo;
        splitf(W[i], hi, lo);
        Th[i] = hi;
        Tl[i] = lo;
    }
}

// ---------------------------------------------------------------------------
// combine4: x += p0+p1+p2+p3 + bias (last layer, before lnf)
// ---------------------------------------------------------------------------
__global__ void __launch_bounds__(256) combine4(const float4* __restrict__ p,
                                                const float* __restrict__ bias,
                                                float4* __restrict__ x, int total4) {
    int i = blockIdx.x * 256 + threadIdx.x;
    if (i < total4) {
        float4 a = p[i], b = p[i + total4];
        float4 c2 = p[i + 2 * total4], d2 = p[i + 3 * total4];
        float4 c = x[i];
        int col = (i & (DD / 4 - 1)) * 4;
        c.x += a.x + b.x + c2.x + d2.x + bias[col];
        c.y += a.y + b.y + c2.y + d2.y + bias[col + 1];
        c.z += a.z + b.z + c2.z + d2.z + bias[col + 2];
        c.w += a.w + b.w + c2.w + d2.w + bias[col + 3];
        x[i] = c;
    }
}

// ---------------------------------------------------------------------------
// combine_ln: x += p0+p1+p2+p3 + cbias; then LayerNorm(x) -> fp16 hi/lo
// ---------------------------------------------------------------------------
__global__ void __launch_bounds__(256) combine_ln(
    const float* __restrict__ part, const float* __restrict__ cbias,
    const float* __restrict__ w, const float* __restrict__ b,
    float* __restrict__ x, u16* __restrict__ oh, u16* __restrict__ ol) {
    int row = blockIdx.x;
    const size_t TOT = (size_t)NR * DD;
    float v[4];
    float s = 0.f, s2 = 0.f;
#pragma unroll
    for (int i = 0; i < 4; i++) {
        int d = threadIdx.x + i * 256;
        size_t o = (size_t)row * DD + d;
        float val = x[o] + part[o] + part[TOT + o] + part[2 * TOT + o]
                  + part[3 * TOT + o] + cbias[d];
        x[o] = val;
        v[i] = val; s += val; s2 += val * val;
    }
#pragma unroll
    for (int o = 16; o; o >>= 1) {
        s  += __shfl_xor_sync(0xffffffffu, s,  o);
        s2 += __shfl_xor_sync(0xffffffffu, s2, o);
    }
    __shared__ float rs[8], rs2[8];
    int warp = threadIdx.x >> 5, lane = threadIdx.x & 31;
    if (!lane) { rs[warp] = s; rs2[warp] = s2; }
    __syncthreads();
    if (threadIdx.x == 0) {
        float a = 0.f, a2 = 0.f;
#pragma unroll
        for (int i = 0; i < 8; i++) { a += rs[i]; a2 += rs2[i]; }
        rs[0] = a; rs2[0] = a2;
    }
    __syncthreads();
    float mean = rs[0] * (1.f / DD);
    float var  = rs2[0] * (1.f / DD) - mean * mean;
    float inv  = rsqrtf(var + 1e-5f);
#pragma unroll
    for (int i = 0; i < 4; i++) {
        int d = threadIdx.x + i * 256;
        float t = (v[i] - mean) * inv * w[d] + b[d];
        u16 hi, lo;
        splitf(t, hi, lo);
        oh[(size_t)row * DD + d] = hi;
        ol[(size_t)row * DD + d] = lo;
    }
}

// ---------------------------------------------------------------------------
// gemm_mma: BM=BN=128, BK=32, split-K via grid.z, warp tile 32x64 (4Mx2N),
// fp16 splits: pass1 f32-acc (hi*hi), pass2 f16-acc (ah*bl, 2^11 scale).
// p3 != 0 adds pass3 (al*bh) for full 3-pass accuracy (LM head).
// 2 CTAs/SM.  epi: 0 f32(+bias); 1 bias+GELU->fp16; 3 raw partial f32
// ---------------------------------------------------------------------------
#define ST_U16 (128 * 40)
#define STAGE_U16 (4 * ST_U16)

__global__ void __launch_bounds__(256, 2) gemm_mma(
    const u16* __restrict__ Ah, const u16* __restrict__ Al,
    const u16* __restrict__ Wh, const u16* __restrict__ Wl,
    const float* __restrict__ bias,
    float* __restrict__ Cf, u16* __restrict__ Ch, u16* __restrict__ Cl,
    int N, int K, int Kfull, int epi, int p3)
{
    extern __shared__ __align__(16) u16 smem_g[];
    const uint32_t sbase = smem_u32(smem_g);

    const int tid = threadIdx.x;
    const int m0 = blockIdx.y * 128, n0 = blockIdx.x * 128;
    const int koff = blockIdx.z * K;
    if (epi == 3)
        Cf += (size_t)blockIdx.z * ((size_t)gridDim.y * 128) * N;
    const int lane = tid & 31, w = tid >> 5;
    const int wm = (w & 3) * 32, wn = (w >> 2) * 64;
    const int lr = lane >> 2;
    const int lc = (lane & 3) * 2;

    const int rowA_l = wm + ((lane >> 3) & 1) * 8 + (lane & 7);
    const int kA_l   = ((lane >> 4) & 1) * 8;
    const int rowB_l = wn + (lane & 7) + ((lane >> 4) & 1) * 8;
    const int kB_l   = ((lane >> 3) & 1) * 8;

    float acc[2][8][4];
    uint32_t acc16[2][8][2];
#pragma unroll
    for (int i = 0; i < 2; i++)
#pragma unroll
        for (int j = 0; j < 8; j++) {
#pragma unroll
            for (int q = 0; q < 4; q++) acc[i][j][q] = 0.f;
            acc16[i][j][0] = 0u;
            acc16[i][j][1] = 0u;
        }

    const int nch = K >> 5;
    const int srow = tid & 127, sc4 = tid >> 7;

    auto stage = [&](int kc, int st) {
        const int kb = koff + (kc << 5);
        const uint32_t base = sbase + (uint32_t)st * (STAGE_U16 * 2);
#pragma unroll
        for (int it = 0; it < 2; it++) {
            int row = srow, c4 = sc4 + it * 2;
            size_t ga = (size_t)(m0 + row) * Kfull + kb + c4 * 8;
            uint32_t da = base + (uint32_t)(row * 40 + c4 * 8) * 2;
            CP_A16(da,                &Ah[ga]);
            CP_A16(da + ST_U16 * 2,   &Al[ga]);
            int n = n0 + row;
            int ok = (n < N);
            size_t gb = (size_t)(ok ? n : 0) * Kfull + kb + c4 * 8;
            uint32_t sz = ok ? 16u : 0u;
            CP_A16Z(da + ST_U16 * 4,  &Wh[gb], sz);
            CP_A16Z(da + ST_U16 * 6,  &Wl[gb], sz);
        }
    };

    stage(0, 0);
    CP_COMMIT();

    for (int kc = 0; kc < nch; kc++) {
        const int st = kc & 1;
        if (kc + 1 < nch) {
            stage(kc + 1, st ^ 1);
            CP_COMMIT();
            CP_WAIT(1);
        } else {
            CP_WAIT(0);
        }
        __syncthreads();

        const uint32_t bA = sbase + (uint32_t)st * (STAGE_U16 * 2);
        const uint32_t bAl = bA + ST_U16 * 2;
        const uint32_t bB = bA + ST_U16 * 4;
        const uint32_t bBl = bA + ST_U16 * 6;

#pragma unroll
        for (int ks = 0; ks < 2; ks++) {
            const int k0 = ks * 16;
#pragma unroll
            for (int j2 = 0; j2 < 4; j2++) {
                uint32_t bh[4], bl[4];
                uint32_t aB = (uint32_t)((rowB_l + j2 * 16) * 40 + k0 + kB_l) * 2;
                ldsm_x4(bh, bB + aB);
                ldsm_x4(bl, bBl + aB);
#pragma unroll
                for (int i = 0; i < 2; i++) {
                    uint32_t ah[4];
                    uint32_t aA = (uint32_t)((rowA_l + i * 16) * 40 + k0 + kA_l) * 2;
                    ldsm_x4(ah, bA + aA);
                    MMA_F32(acc[i][j2 * 2],     ah, bh);
                    MMA_F32(acc[i][j2 * 2 + 1], ah, bh + 2);
                    MMA_F16(acc16[i][j2 * 2],     ah, bl);
                    MMA_F16(acc16[i][j2 * 2 + 1], ah, bl + 2);
                    if (p3) {
                        uint32_t al[4];
                        ldsm_x4(al, bAl + aA);
                        MMA_F16(acc16[i][j2 * 2],     al, bh);
                        MMA_F16(acc16[i][j2 * 2 + 1], al, bh + 2);
                    }
                }
            }
        }
        __syncthreads();
    }

    // ---- epilogue: C = acc32 + 2^-11 * float(acc16) ----
#pragma unroll
    for (int i = 0; i < 2; i++)
#pragma unroll
        for (int j = 0; j < 8; j++) {
            float2 c01 = __half22float2(*reinterpret_cast<__half2*>(&acc16[i][j][0]));
            float2 c23 = __half22float2(*reinterpret_cast<__half2*>(&acc16[i][j][1]));
            float cv[4] = {acc[i][j][0] + LO_INV * c01.x,
                           acc[i][j][1] + LO_INV * c01.y,
                           acc[i][j][2] + LO_INV * c23.x,
                           acc[i][j][3] + LO_INV * c23.y};
#pragma unroll
            for (int half = 0; half < 2; half++) {
                int row = m0 + wm + i * 16 + lr + half * 8;
                int col = n0 + wn + j * 8 + lc;
                float v0 = cv[half * 2 + 0];
                float v1 = cv[half * 2 + 1];
                size_t o = (size_t)row * N + col;
                if (epi == 1) {
                    float t0 = fast_gelu(v0 + bias[col]);
                    float t1 = fast_gelu(v1 + bias[col + 1]);
                    u16 h0, l0, h1, l1;
                    splitf(t0, h0, l0);
                    splitf(t1, h1, l1);
                    Ch[o] = h0; Cl[o] = l0;
                    Ch[o + 1] = h1; Cl[o + 1] = l1;
                } else if (epi == 3) {
                    Cf[o] = v0;
                    Cf[o + 1] = v1;
                } else {
                    if (bias) { v0 += bias[col]; v1 += (col + 1 < N) ? bias[col + 1] : 0.f; }
                    if (col < N) Cf[o] = v0;
                    if (col + 1 < N) Cf[o + 1] = v1;
                }
            }
        }
}

// ---------------------------------------------------------------------------
// Embedding
// ---------------------------------------------------------------------------
__global__ void embed_kernel(const float* __restrict__ states,
                             const int* __restrict__ actions,
                             const float* __restrict__ rtgs,
                             const int* __restrict__ tsteps,
                             const float* __restrict__ se_w, const float* __restrict__ se_b,
                             const float* __restrict__ re_w, const float* __restrict__ re_b,
                             const float* __restrict__ ae,
                             const float* __restrict__ pe,
                             const float* __restrict__ gpe) {
    int s = blockIdx.x;
    int b = blockIdx.y;
    int t = s / 3, kind = s % 3;
    int ts = tsteps[b];
    const float* g = gpe + (size_t)ts * DD;
    const float* p = pe + (size_t)s * DD;
    float* out = g_x + ((size_t)(b * SS + s)) * DD;

    if (kind == 0) {
        float r = rtgs[b * TT + t];
        for (int d = threadIdx.x; d < DD; d += blockDim.x)
            out[d] = fmaf(r, re_w[d], re_b[d]) + g[d] + p[d];
    } else if (kind == 1) {
        float st = states[b * TT + t];
        for (int d = threadIdx.x; d < DD; d += blockDim.x)
            out[d] = fmaf(st, se_w[d], se_b[d]) + g[d] + p[d];
    } else {
        int a = actions[b * TT + t];
        const float* av = ae + (size_t)a * DD;
        for (int d = threadIdx.x; d < DD; d += blockDim.x)
            out[d] = av[d] + g[d] + p[d];
    }
}

// ---------------------------------------------------------------------------
// LayerNorm (f32 in -> fp16 hi/lo out)
// ---------------------------------------------------------------------------
__global__ void __launch_bounds__(256) ln_kernel(const float* __restrict__ x,
                                                 const float* __restrict__ w,
                                                 const float* __restrict__ b,
                                                 u16* __restrict__ oh,
                                                 u16* __restrict__ ol) {
    int row = blockIdx.x;
    const float* xr = x + (size_t)row * DD;
    float v[4];
    float s = 0.f, s2 = 0.f;
#pragma unroll
    for (int i = 0; i < 4; i++) {
        float val = xr[threadIdx.x + i * 256];
        v[i] = val; s += val; s2 += val * val;
    }
#pragma unroll
    for (int o = 16; o; o >>= 1) {
        s  += __shfl_xor_sync(0xffffffffu, s,  o);
        s2 += __shfl_xor_sync(0xffffffffu, s2, o);
    }
    __shared__ float rs[8], rs2[8];
    int warp = threadIdx.x >> 5, lane = threadIdx.x & 31;
    if (!lane) { rs[warp] = s; rs2[warp] = s2; }
    __syncthreads();
    if (threadIdx.x == 0) {
        float a = 0.f, a2 = 0.f;
#pragma unroll
        for (int i = 0; i < 8; i++) { a += rs[i]; a2 += rs2[i]; }
        rs[0] = a; rs2[0] = a2;
    }
    __syncthreads();
    float mean = rs[0] * (1.f / DD);
    float var  = rs2[0] * (1.f / DD) - mean * mean;
    float inv  = rsqrtf(var + 1e-5f);
#pragma unroll
    for (int i = 0; i < 4; i++) {
        int d = threadIdx.x + i * 256;
        float t = (v[i] - mean) * inv * w[d] + b[d];
        u16 hi, lo;
        splitf(t, hi, lo);
        oh[(size_t)row * DD + d] = hi;
        ol[(size_t)row * DD + d] = lo;
    }
}

// Final LN with state-row gather
__global__ void __launch_bounds__(256) lnf_kernel(const float* __restrict__ w,
                                                  const float* __restrict__ b) {
    int m = blockIdx.x;
    int bb = m / TT, t = m % TT;
    int src = bb * SS + 3 * t + 1;
    const float* xr = g_x + (size_t)src * DD;
    float v[4];
    float s = 0.f, s2 = 0.f;
#pragma unroll
    for (int i = 0; i < 4; i++) {
        float val = xr[threadIdx.x + i * 256];
        v[i] = val; s += val; s2 += val * val;
    }
#pragma unroll
    for (int o = 16; o; o >>= 1) {
        s  += __shfl_xor_sync(0xffffffffu, s,  o);
        s2 += __shfl_xor_sync(0xffffffffu, s2, o);
    }
    __shared__ float rs[8], rs2[8];
    int warp = threadIdx.x >> 5, lane = threadIdx.x & 31;
    if (!lane) { rs[warp] = s; rs2[warp] = s2; }
    __syncthreads();
    if (threadIdx.x == 0) {
        float a = 0.f, a2 = 0.f;
#pragma unroll
        for (int i = 0; i < 8; i++) { a += rs[i]; a2 += rs2[i]; }
        rs[0] = a; rs2[0] = a2;
    }
    __syncthreads();
    float mean = rs[0] * (1.f / DD);
    float var  = rs2[0] * (1.f / DD) - mean * mean;
    float inv  = rsqrtf(var + 1e-5f);
#pragma unroll
    for (int i = 0; i < 4; i++) {
        int d = threadIdx.x + i * 256;
        float t2 = (v[i] - mean) * inv * w[d] + b[d];
        u16 hi, lo;
        splitf(t2, hi, lo);
        g_h_hi[(size_t)m * DD + d] = hi;
        g_h_lo[(size_t)m * DD + d] = lo;
    }
}

// ---------------------------------------------------------------------------
// Flash attention (f32 compute, fp16 hi/lo output)
// ---------------------------------------------------------------------------
__global__ void __launch_bounds__(128) attn_flash() {
    extern __shared__ float sm[];
    float* Qs = sm;
    float* Ks = sm + 64 * QS;
    float* Ps = sm + 2 * 64 * QS;
    float* Vs = sm + 3 * 64 * QS;

    const int qt = blockIdx.x, h = blockIdx.y, b = blockIdx.z;
    const float* base = g_qkv + (size_t)b * SS * (3 * DD);
    const int tid = threadIdx.x;
    const int tq = tid >> 3, tk = tid & 7;

    for (int i = tid; i < 1024; i += 128) {
        int r = i >> 4, dg = i & 15;
        float4 v = *reinterpret_cast<const float4*>(
            &base[(size_t)(qt * 64 + r) * (3 * DD) + h * HDIM + dg * 4]);
        Qs[(dg * 4 + 0) * QS + r] = v.x;
        Qs[(dg * 4 + 1) * QS + r] = v.y;
        Qs[(dg * 4 + 2) * QS + r] = v.z;
        Qs[(dg * 4 + 3) * QS + r] = v.w;
    }

    float m_i[4], l_i[4], O[4][8];
#pragma unroll
    for (int i = 0; i < 4; i++) {
        m_i[i] = -1e30f; l_i[i] = 0.f;
#pragma unroll
        for (int j = 0; j < 8; j++) O[i][j] = 0.f;
    }

    for (int kt = 0; kt <= qt; kt++) {
        __syncthreads();
        for (int i = tid; i < 1024; i += 128) {
            int r = i >> 4, dg = i & 15;
            const float* krow = &base[(size_t)(kt * 64 + r) * (3 * DD) + DD + h * HDIM];
            float4 kv = *reinterpret_cast<const float4*>(krow + dg * 4);
            Ks[(dg * 4 + 0) * QS + r] = kv.x;
            Ks[(dg * 4 + 1) * QS + r] = kv.y;
            Ks[(dg * 4 + 2) * QS + r] = kv.z;
            Ks[(dg * 4 + 3) * QS + r] = kv.w;
            float4 vv = *reinterpret_cast<const float4*>(
                &base[(size_t)(kt * 64 + r) * (3 * DD) + 2 * DD + h * HDIM + dg * 4]);
            *reinterpret_cast<float4*>(&Vs[r * 64 + dg * 4]) = vv;
        }
        __syncthreads();

        float s[4][8];
#pragma unroll
        for (int i = 0; i < 4; i++)
#pragma unroll
            for (int j = 0; j < 8; j++) s[i][j] = 0.f;
#pragma unroll 8
        for (int d = 0; d < 64; d++) {
            float4 a = *reinterpret_cast<const float4*>(&Qs[d * QS + tq * 4]);
            float4 b0 = *reinterpret_cast<const float4*>(&Ks[d * QS + tk * 8]);
            float4 b1 = *reinterpret_cast<const float4*>(&Ks[d * QS + tk * 8 + 4]);
            float ar[4] = {a.x, a.y, a.z, a.w};
            float br[8] = {b0.x, b0.y, b0.z, b0.w, b1.x, b1.y, b1.z, b1.w};
#pragma unroll
            for (int i = 0; i < 4; i++)
#pragma unroll
                for (int j = 0; j < 8; j++)
                    s[i][j] = fmaf(ar[i], br[j], s[i][j]);
        }
        const bool diag = (kt == qt);
#pragma unroll
        for (int i = 0; i < 4; i++) {
            int qg = qt * 64 + tq * 4 + i;
#pragma unroll
            for (int j = 0; j < 8; j++) {
                int kg = kt * 64 + tk * 8 + j;
                s[i][j] = (diag && kg > qg) ? -1e30f : s[i][j] * 0.125f;
            }
        }
        float e[4][8];
#pragma unroll
        for (int i = 0; i < 4; i++) {
            float rm = s[i][0];
#pragma unroll
            for (int j = 1; j < 8; j++) rm = fmaxf(rm, s[i][j]);
            rm = fmaxf(rm, __shfl_xor_sync(0xffffffffu, rm, 1));
            rm = fmaxf(rm, __shfl_xor_sync(0xffffffffu, rm, 2));
            rm = fmaxf(rm, __shfl_xor_sync(0xffffffffu, rm, 4));
            float newm = fmaxf(m_i[i], rm);
            float f = __expf(m_i[i] - newm);
            float es = 0.f;
#pragma unroll
            for (int j = 0; j < 8; j++) {
                float ev = __expf(s[i][j] - newm);
                e[i][j] = ev; es += ev;
            }
            es += __shfl_xor_sync(0xffffffffu, es, 1);
            es += __shfl_xor_sync(0xffffffffu, es, 2);
            es += __shfl_xor_sync(0xffffffffu, es, 4);
            l_i[i] = l_i[i] * f + es;
            m_i[i] = newm;
#pragma unroll
            for (int j = 0; j < 8; j++) O[i][j] *= f;
        }
#pragma unroll
        for (int j = 0; j < 8; j++)
#pragma unroll
            for (int i = 0; i < 4; i++)
                Ps[(tk * 8 + j) * QS + tq * 4 + i] = e[i][j];
        __syncthreads();
#pragma unroll 8
        for (int k = 0; k < 64; k++) {
            float4 a = *reinterpret_cast<const float4*>(&Ps[k * QS + tq * 4]);
            float4 b0 = *reinterpret_cast<const float4*>(&Vs[k * 64 + tk * 8]);
            float4 b1 = *reinterpret_cast<const float4*>(&Vs[k * 64 + tk * 8 + 4]);
            float ar[4] = {a.x, a.y, a.z, a.w};
            float br[8] = {b0.x, b0.y, b0.z, b0.w, b1.x, b1.y, b1.z, b1.w};
#pragma unroll
            for (int i = 0; i < 4; i++)
#pragma unroll
                for (int j = 0; j < 8; j++)
                    O[i][j] = fmaf(ar[i], br[j], O[i][j]);
        }
    }

#pragma unroll
    for (int i = 0; i < 4; i++) {
        float inv = 1.f / l_i[i];
        int q = qt * 64 + tq * 4 + i;
        size_t o = ((size_t)(b * SS + q)) * DD + h * HDIM + tk * 8;
#pragma unroll
        for (int j = 0; j < 8; j++) {
            u16 hi, lo;
            splitf(O[i][j] * inv, hi, lo);
            g_y_hi[o + j] = hi;
            g_y_lo[o + j] = lo;
        }
    }
}

// ---------------------------------------------------------------------------
// Launcher
// ---------------------------------------------------------------------------
extern "C" void kernel_launch(void* const* d_in, const int* in_sizes, int n_in,
                              void* d_out, int out_size) {
    const float* states  = (const float*)d_in[0];
    const int*   actions = (const int*)  d_in[1];
    const float* rtgs    = (const float*)d_in[2];
    const int*   tsteps  = (const int*)  d_in[3];
    const float* se_w = (const float*)d_in[4],  *se_b = (const float*)d_in[5];
    const float* re_w = (const float*)d_in[6],  *re_b = (const float*)d_in[7];
    const float* ae   = (const float*)d_in[8];
    const float* pe   = (const float*)d_in[9];
    const float* gpe  = (const float*)d_in[10];
    const float* ln1_w = (const float*)d_in[11], *ln1_b = (const float*)d_in[12];
    const float* qkv_w = (const float*)d_in[13], *qkv_b = (const float*)d_in[14];
    const float* proj_w= (const float*)d_in[15], *proj_b= (const float*)d_in[16];
    const float* ln2_w = (const float*)d_in[17], *ln2_b = (const float*)d_in[18];
    const float* fc_w  = (const float*)d_in[19], *fc_b  = (const float*)d_in[20];
    const float* fcp_w = (const float*)d_in[21], *fcp_b = (const float*)d_in[22];
    const float* lnf_w = (const float*)d_in[23], *lnf_b = (const float*)d_in[24];
    const float* lm_w  = (const float*)d_in[25];
    float* out = (float*)d_out;

    float *x, *qkv, *part;
    u16 *hh, *hl, *yh, *yl, *ffh, *ffl;
    u16 *wqh, *wql, *wph, *wpl, *wfh, *wfl, *wgh, *wgl, *wlh, *wll;
    cudaGetSymbolAddress((void**)&x,    g_x);
    cudaGetSymbolAddress((void**)&qkv,  g_qkv);
    cudaGetSymbolAddress((void**)&part, g_part);
    cudaGetSymbolAddress((void**)&hh,   g_h_hi);
    cudaGetSymbolAddress((void**)&hl,   g_h_lo);
    cudaGetSymbolAddress((void**)&yh,   g_y_hi);
    cudaGetSymbolAddress((void**)&yl,   g_y_lo);
    cudaGetSymbolAddress((void**)&ffh,  g_ff_hi);
    cudaGetSymbolAddress((void**)&ffl,  g_ff_lo);
    cudaGetSymbolAddress((void**)&wqh,  w_qkv_h);
    cudaGetSymbolAddress((void**)&wql,  w_qkv_l);
    cudaGetSymbolAddress((void**)&wph,  w_proj_h);
    cudaGetSymbolAddress((void**)&wpl,  w_proj_l);
    cudaGetSymbolAddress((void**)&wfh,  w_fc_h);
    cudaGetSymbolAddress((void**)&wfl,  w_fc_l);
    cudaGetSymbolAddress((void**)&wgh,  w_fcp_h);
    cudaGetSymbolAddress((void**)&wgl,  w_fcp_l);
    cudaGetSymbolAddress((void**)&wlh,  w_lm_h);
    cudaGetSymbolAddress((void**)&wll,  w_lm_l);

    const int SMEM_ATTN = (3 * 64 * QS + 64 * 64) * 4;   // 68608
    const int SMEM_GEMM = 2 * STAGE_U16 * 2;             // 81920
    cudaFuncSetAttribute(attn_flash,
                         cudaFuncAttributeMaxDynamicSharedMemorySize, SMEM_ATTN);
    cudaFuncSetAttribute(gemm_mma,
                         cudaFuncAttributeMaxDynamicSharedMemorySize, SMEM_GEMM);

    const int total4 = NR * DD / 4;
    const int cgrid = (total4 + 255) / 256;

    // Launch order: #4 is the layer-0 QKV GEMM (ncu profiles the 4th launch).
    wconv<<<dim3(3072 / 32, 1024 / 32, LL), dim3(32, 8)>>>(qkv_w, wqh, wql, 1024, 3072); // 1
    embed_kernel<<<dim3(SS, BB), 256>>>(states, actions, rtgs, tsteps,
                                        se_w, se_b, re_w, re_b, ae, pe, gpe);            // 2
    ln_kernel<<<NR, 256>>>(x, ln1_w, ln1_b, hh, hl);                                     // 3

    for (int l = 0; l < LL; l++) {
        gemm_mma<<<dim3(3072 / 128, NR / 128), 256, SMEM_GEMM>>>(                         // 4 on l=0
            hh, hl, wqh + (size_t)l * 3072 * 1024, wql + (size_t)l * 3072 * 1024,
            qkv_b + (size_t)l * 3072, qkv, nullptr, nullptr,
            3072, 1024, 1024, 0, 0);
        if (l == 0) {
            wconv<<<dim3(1024 / 32, 1024 / 32, LL), dim3(32, 8)>>>(proj_w, wph, wpl, 1024, 1024);
            wconv<<<dim3(4096 / 32, 1024 / 32, LL), dim3(32, 8)>>>(fc_w, wfh, wfl, 1024, 4096);
            wconv<<<dim3(1024 / 32, 4096 / 32, LL), dim3(32, 8)>>>(fcp_w, wgh, wgl, 4096, 1024);
            lmconv<<<(SZ_LM + 255) / 256, 256>>>(lm_w, wlh, wll, SZ_LM);
        }
        attn_flash<<<dim3(SS / 64, HH, BB), 128, SMEM_ATTN>>>();
        gemm_mma<<<dim3(1024 / 128, NR / 128, 4), 256, SMEM_GEMM>>>(
            yh, yl, wph + (size_t)l * 1024 * 1024, wpl + (size_t)l * 1024 * 1024,
            nullptr, part, nullptr, nullptr, 1024, 256, 1024, 3, 0);
        combine_ln<<<NR, 256>>>(part, proj_b + (size_t)l * 1024,
                                ln2_w + l * DD, ln2_b + l * DD, x, hh, hl);
        gemm_mma<<<dim3(4096 / 128, NR / 128), 256, SMEM_GEMM>>>(
            hh, hl, wfh + (size_t)l * 4096 * 1024, wfl + (size_t)l * 4096 * 1024,
            fc_b + (size_t)l * 4096, nullptr, ffh, ffl,
            4096, 1024, 1024, 1, 0);
        gemm_mma<<<dim3(1024 / 128, NR / 128, 4), 256, SMEM_GEMM>>>(
            ffh, ffl, wgh + (size_t)l * 1024 * 4096, wgl + (size_t)l * 1024 * 4096,
            nullptr, part, nullptr, nullptr, 1024, 1024, 4096, 3, 0);
        if (l < LL - 1) {
            combine_ln<<<NR, 256>>>(part, fcp_b + (size_t)l * 1024,
                                    ln1_w + (l + 1) * DD, ln1_b + (l + 1) * DD,
                                    x, hh, hl);
        } else {
            combine4<<<cgrid, 256>>>((const float4*)part, fcp_b + (size_t)l * 1024,
                                     (float4*)x, total4);
            lnf_kernel<<<BB * TT, 256>>>(lnf_w, lnf_b);
        }
    }

    gemm_mma<<<dim3((VV + 127) / 128, (BB * TT) / 128), 256, SMEM_GEMM>>>(
        hh, hl, wlh, wll, nullptr, out, nullptr, nullptr,
        VV, 1024, 1024, 0, 1);
}

// round 15
// speedup vs baseline: 1.6597x; 1.0875x over previous
#include <cuda_runtime.h>
#include <cuda_fp16.h>
#include <math.h>
#include <stdint.h>

typedef unsigned short u16;

// Problem constants
#define LL 12
#define DD 1024
#define HH 16
#define VV 50257
#define TT 256
#define BB 2
#define SS 768
#define HDIM 64
#define NR (BB * SS)   // 1536 rows

#define QS 68   // attention smem row stride (floats)
#define LO_SCALE 2048.0f
#define LO_INV 4.8828125e-4f

// ---------------------------------------------------------------------------
// Device-global scratch
// ---------------------------------------------------------------------------
__device__ __align__(16) float g_x[NR * DD];
__device__ __align__(16) float g_qkv[NR * 3 * DD];
__device__ __align__(16) float g_part[4 * NR * DD];
__device__ __align__(16) u16 g_h_hi[NR * DD],  g_h_lo[NR * DD];
__device__ __align__(16) u16 g_y_hi[NR * DD],  g_y_lo[NR * DD];
__device__ __align__(16) u16 g_ff_hi[NR * 4 * DD], g_ff_lo[NR * 4 * DD];

#define SZ_QKV (LL * 3072 * 1024)
#define SZ_PROJ (LL * 1024 * 1024)
#define SZ_FC  (LL * 4096 * 1024)
#define SZ_FCP (LL * 1024 * 4096)
#define SZ_LM  (VV * 1024)
__device__ __align__(16) u16 w_qkv_h[SZ_QKV], w_qkv_l[SZ_QKV];
__device__ __align__(16) u16 w_proj_h[SZ_PROJ], w_proj_l[SZ_PROJ];
__device__ __align__(16) u16 w_fc_h[SZ_FC],   w_fc_l[SZ_FC];
__device__ __align__(16) u16 w_fcp_h[SZ_FCP], w_fcp_l[SZ_FCP];
__device__ __align__(16) u16 w_lm_h[SZ_LM],   w_lm_l[SZ_LM];

// ---------------------------------------------------------------------------
// helpers: fp16 split, lo scaled by 2^11
// ---------------------------------------------------------------------------
__device__ __forceinline__ void splitf(float v, u16& hi, u16& lo) {
    __half h = __float2half_rn(v);
    float r = (v - __half2float(h)) * LO_SCALE;
    hi = __half_as_ushort(h);
    lo = __half_as_ushort(__float2half_rn(r));
}
__device__ __forceinline__ uint32_t smem_u32(const void* p) {
    uint32_t a;
    asm("{ .reg .u64 t; cvta.to.shared.u64 t, %1; cvt.u32.u64 %0, t; }"
        : "=r"(a) : "l"(p));
    return a;
}
__device__ __forceinline__ float fast_gelu(float x) {
    float u = 0.7978845608028654f * (x + 0.044715f * x * x * x);
    float th = 1.f - 2.f / (__expf(2.f * u) + 1.f);
    return 0.5f * x * (1.f + th);
}

#define CP_A16(dst, src) \
    asm volatile("cp.async.cg.shared.global [%0], [%1], 16;" \
                 :: "r"(dst), "l"(src))
#define CP_A16Z(dst, src, sz) \
    asm volatile("cp.async.cg.shared.global [%0], [%1], 16, %2;" \
                 :: "r"(dst), "l"(src), "r"(sz))
#define CP_COMMIT() asm volatile("cp.async.commit_group;")
#define CP_WAIT(n)  asm volatile("cp.async.wait_group %0;" :: "n"(n))

__device__ __forceinline__ void ldsm_x4(uint32_t* r, uint32_t addr) {
    asm volatile("ldmatrix.sync.aligned.m8n8.x4.shared.b16 {%0,%1,%2,%3}, [%4];"
                 : "=r"(r[0]), "=r"(r[1]), "=r"(r[2]), "=r"(r[3]) : "r"(addr));
}
#define MMA_F32(c, a, b) \
    asm volatile("mma.sync.aligned.m16n8k16.row.col.f32.f16.f16.f32 " \
                 "{%0,%1,%2,%3}, {%4,%5,%6,%7}, {%8,%9}, {%0,%1,%2,%3};" \
                 : "+f"((c)[0]), "+f"((c)[1]), "+f"((c)[2]), "+f"((c)[3]) \
                 : "r"((a)[0]), "r"((a)[1]), "r"((a)[2]), "r"((a)[3]), \
                   "r"((b)[0]), "r"((b)[1]))
#define MMA_F16(c, a, b) \
    asm volatile("mma.sync.aligned.m16n8k16.row.col.f16.f16.f16.f16 " \
                 "{%0,%1}, {%2,%3,%4,%5}, {%6,%7}, {%0,%1};" \
                 : "+r"((c)[0]), "+r"((c)[1]) \
                 : "r"((a)[0]), "r"((a)[1]), "r"((a)[2]), "r"((a)[3]), \
                   "r"((b)[0]), "r"((b)[1]))

// ---------------------------------------------------------------------------
// Weight conversion: W[K,N] f32 -> T[N,K] fp16 hi/lo(x2048)
// ---------------------------------------------------------------------------
__global__ void __launch_bounds__(256) wconv(const float* __restrict__ W,
                                             u16* __restrict__ Th,
                                             u16* __restrict__ Tl,
                                             int K, int N) {
    __shared__ float tile[32][33];
    const size_t lof = (size_t)blockIdx.z * K * N;
    const float* Wp = W + lof;
    u16* Thp = Th + lof;
    u16* Tlp = Tl + lof;
    const int n0 = blockIdx.x * 32, k0 = blockIdx.y * 32;
    const int tx = threadIdx.x, ty = threadIdx.y;
#pragma unroll
    for (int i = 0; i < 4; i++)
        tile[ty + i * 8][tx] = Wp[(size_t)(k0 + ty + i * 8) * N + n0 + tx];
    __syncthreads();
#pragma unroll
    for (int i = 0; i < 4; i++) {
        float v = tile[tx][ty + i * 8];
        u16 hi, lo;
        splitf(v, hi, lo);
        size_t o = (size_t)(n0 + ty + i * 8) * K + k0 + tx;
        Thp[o] = hi;
        Tlp[o] = lo;
    }
}

__global__ void lmconv(const float* __restrict__ W, u16* __restrict__ Th,
                       u16* __restrict__ Tl, int total) {
    int i = blockIdx.x * 256 + threadIdx.x;
    if (i < total) {
        u16 hi, lo;
        splitf(W[i], hi, lo);
        Th[i] = hi;
        Tl[i] = lo;
    }
}

// ---------------------------------------------------------------------------
// combine4: x += p0+p1+p2+p3 + bias (last layer, before lnf)
// ---------------------------------------------------------------------------
__global__ void __launch_bounds__(256) combine4(const float4* __restrict__ p,
                                                const float* __restrict__ bias,
                                                float4* __restrict__ x, int total4) {
    int i = blockIdx.x * 256 + threadIdx.x;
    if (i < total4) {
        float4 a = p[i], b = p[i + total4];
        float4 c2 = p[i + 2 * total4], d2 = p[i + 3 * total4];
        float4 c = x[i];
        int col = (i & (DD / 4 - 1)) * 4;
        c.x += a.x + b.x + c2.x + d2.x + bias[col];
        c.y += a.y + b.y + c2.y + d2.y + bias[col + 1];
        c.z += a.z + b.z + c2.z + d2.z + bias[col + 2];
        c.w += a.w + b.w + c2.w + d2.w + bias[col + 3];
        x[i] = c;
    }
}

// ---------------------------------------------------------------------------
// combine_ln: x += p0+p1+p2+p3 + cbias; then LayerNorm(x) -> fp16 hi/lo
// ---------------------------------------------------------------------------
__global__ void __launch_bounds__(256) combine_ln(
    const float* __restrict__ part, const float* __restrict__ cbias,
    const float* __restrict__ w, const float* __restrict__ b,
    float* __restrict__ x, u16* __restrict__ oh, u16* __restrict__ ol) {
    int row = blockIdx.x;
    const size_t TOT = (size_t)NR * DD;
    float v[4];
    float s = 0.f, s2 = 0.f;
#pragma unroll
    for (int i = 0; i < 4; i++) {
        int d = threadIdx.x + i * 256;
        size_t o = (size_t)row * DD + d;
        float val = x[o] + part[o] + part[TOT + o] + part[2 * TOT + o]
                  + part[3 * TOT + o] + cbias[d];
        x[o] = val;
        v[i] = val; s += val; s2 += val * val;
    }
#pragma unroll
    for (int o = 16; o; o >>= 1) {
        s  += __shfl_xor_sync(0xffffffffu, s,  o);
        s2 += __shfl_xor_sync(0xffffffffu, s2, o);
    }
    __shared__ float rs[8], rs2[8];
    int warp = threadIdx.x >> 5, lane = threadIdx.x & 31;
    if (!lane) { rs[warp] = s; rs2[warp] = s2; }
    __syncthreads();
    if (threadIdx.x == 0) {
        float a = 0.f, a2 = 0.f;
#pragma unroll
        for (int i = 0; i < 8; i++) { a += rs[i]; a2 += rs2[i]; }
        rs[0] = a; rs2[0] = a2;
    }
    __syncthreads();
    float mean = rs[0] * (1.f / DD);
    float var  = rs2[0] * (1.f / DD) - mean * mean;
    float inv  = rsqrtf(var + 1e-5f);
#pragma unroll
    for (int i = 0; i < 4; i++) {
        int d = threadIdx.x + i * 256;
        float t = (v[i] - mean) * inv * w[d] + b[d];
        u16 hi, lo;
        splitf(t, hi, lo);
        oh[(size_t)row * DD + d] = hi;
        ol[(size_t)row * DD + d] = lo;
    }
}

// ---------------------------------------------------------------------------
// gemm_mma: BM=BN=128, BK=32, split-K via grid.z, warp tile 32x64 (4Mx2N).
// Minimum-LDSM inner loop: A fragments cached per ks (ah0/ah1), B streamed.
// Pass1 hi*hi f32-acc; pass2 ah*bl f16-acc (2^11 scale); p3 adds al*bh (LM).
// 2 CTAs/SM.  epi: 0 f32(+bias); 1 bias+GELU->fp16; 3 raw partial f32
// ---------------------------------------------------------------------------
#define ST_U16 (128 * 40)
#define STAGE_U16 (4 * ST_U16)

__global__ void __launch_bounds__(256, 2) gemm_mma(
    const u16* __restrict__ Ah, const u16* __restrict__ Al,
    const u16* __restrict__ Wh, const u16* __restrict__ Wl,
    const float* __restrict__ bias,
    float* __restrict__ Cf, u16* __restrict__ Ch, u16* __restrict__ Cl,
    int N, int K, int Kfull, int epi, int p3)
{
    extern __shared__ __align__(16) u16 smem_g[];
    const uint32_t sbase = smem_u32(smem_g);

    const int tid = threadIdx.x;
    const int m0 = blockIdx.y * 128, n0 = blockIdx.x * 128;
    const int koff = blockIdx.z * K;
    if (epi == 3)
        Cf += (size_t)blockIdx.z * ((size_t)gridDim.y * 128) * N;
    const int lane = tid & 31, w = tid >> 5;
    const int wm = (w & 3) * 32, wn = (w >> 2) * 64;
    const int lr = lane >> 2;
    const int lc = (lane & 3) * 2;

    const int rowA_l = wm + ((lane >> 3) & 1) * 8 + (lane & 7);
    const int kA_l   = ((lane >> 4) & 1) * 8;
    const int rowB_l = wn + (lane & 7) + ((lane >> 4) & 1) * 8;
    const int kB_l   = ((lane >> 3) & 1) * 8;

    float acc[2][8][4];
    uint32_t acc16[2][8][2];
#pragma unroll
    for (int i = 0; i < 2; i++)
#pragma unroll
        for (int j = 0; j < 8; j++) {
#pragma unroll
            for (int q = 0; q < 4; q++) acc[i][j][q] = 0.f;
            acc16[i][j][0] = 0u;
            acc16[i][j][1] = 0u;
        }

    const int nch = K >> 5;
    const int srow = tid & 127, sc4 = tid >> 7;

    auto stage = [&](int kc, int st) {
        const int kb = koff + (kc << 5);
        const uint32_t base = sbase + (uint32_t)st * (STAGE_U16 * 2);
#pragma unroll
        for (int it = 0; it < 2; it++) {
            int row = srow, c4 = sc4 + it * 2;
            size_t ga = (size_t)(m0 + row) * Kfull + kb + c4 * 8;
            uint32_t da = base + (uint32_t)(row * 40 + c4 * 8) * 2;
            CP_A16(da,                &Ah[ga]);
            CP_A16(da + ST_U16 * 2,   &Al[ga]);
            int n = n0 + row;
            int ok = (n < N);
            size_t gb = (size_t)(ok ? n : 0) * Kfull + kb + c4 * 8;
            uint32_t sz = ok ? 16u : 0u;
            CP_A16Z(da + ST_U16 * 4,  &Wh[gb], sz);
            CP_A16Z(da + ST_U16 * 6,  &Wl[gb], sz);
        }
    };

    stage(0, 0);
    CP_COMMIT();

    for (int kc = 0; kc < nch; kc++) {
        const int st = kc & 1;
        if (kc + 1 < nch) {
            stage(kc + 1, st ^ 1);
            CP_COMMIT();
            CP_WAIT(1);
        } else {
            CP_WAIT(0);
        }
        __syncthreads();

        const uint32_t bA = sbase + (uint32_t)st * (STAGE_U16 * 2);
        const uint32_t bAl = bA + ST_U16 * 2;
        const uint32_t bB = bA + ST_U16 * 4;
        const uint32_t bBl = bA + ST_U16 * 6;

#pragma unroll
        for (int ks = 0; ks < 2; ks++) {
            const int k0 = ks * 16;
            const uint32_t aA0 = (uint32_t)(rowA_l * 40 + k0 + kA_l) * 2;
            const uint32_t aA1 = (uint32_t)((rowA_l + 16) * 40 + k0 + kA_l) * 2;
            uint32_t ah0[4], ah1[4];
            ldsm_x4(ah0, bA + aA0);
            ldsm_x4(ah1, bA + aA1);
            // pass 1: hi*hi f32-acc (B streamed)
#pragma unroll
            for (int j2 = 0; j2 < 4; j2++) {
                uint32_t bf[4];
                uint32_t aB = (uint32_t)((rowB_l + j2 * 16) * 40 + k0 + kB_l) * 2;
                ldsm_x4(bf, bB + aB);
                MMA_F32(acc[0][j2 * 2],     ah0, bf);
                MMA_F32(acc[0][j2 * 2 + 1], ah0, bf + 2);
                MMA_F32(acc[1][j2 * 2],     ah1, bf);
                MMA_F32(acc[1][j2 * 2 + 1], ah1, bf + 2);
            }
            // pass 2: hi*lo f16-acc (B-lo streamed)
#pragma unroll
            for (int j2 = 0; j2 < 4; j2++) {
                uint32_t bf[4];
                uint32_t aB = (uint32_t)((rowB_l + j2 * 16) * 40 + k0 + kB_l) * 2;
                ldsm_x4(bf, bBl + aB);
                MMA_F16(acc16[0][j2 * 2],     ah0, bf);
                MMA_F16(acc16[0][j2 * 2 + 1], ah0, bf + 2);
                MMA_F16(acc16[1][j2 * 2],     ah1, bf);
                MMA_F16(acc16[1][j2 * 2 + 1], ah1, bf + 2);
            }
            // pass 3 (LM head only): lo*hi f16-acc (reuse ah regs for A-lo)
            if (p3) {
                ldsm_x4(ah0, bAl + aA0);
                ldsm_x4(ah1, bAl + aA1);
#pragma unroll
                for (int j2 = 0; j2 < 4; j2++) {
                    uint32_t bf[4];
                    uint32_t aB = (uint32_t)((rowB_l + j2 * 16) * 40 + k0 + kB_l) * 2;
                    ldsm_x4(bf, bB + aB);
                    MMA_F16(acc16[0][j2 * 2],     ah0, bf);
                    MMA_F16(acc16[0][j2 * 2 + 1], ah0, bf + 2);
                    MMA_F16(acc16[1][j2 * 2],     ah1, bf);
                    MMA_F16(acc16[1][j2 * 2 + 1], ah1, bf + 2);
                }
            }
        }
        __syncthreads();
    }

    // ---- epilogue: C = acc32 + 2^-11 * float(acc16) ----
#pragma unroll
    for (int i = 0; i < 2; i++)
#pragma unroll
        for (int j = 0; j < 8; j++) {
            float2 c01 = __half22float2(*reinterpret_cast<__half2*>(&acc16[i][j][0]));
            float2 c23 = __half22float2(*reinterpret_cast<__half2*>(&acc16[i][j][1]));
            float cv[4] = {acc[i][j][0] + LO_INV * c01.x,
                           acc[i][j][1] + LO_INV * c01.y,
                           acc[i][j][2] + LO_INV * c23.x,
                           acc[i][j][3] + LO_INV * c23.y};
#pragma unroll
            for (int half = 0; half < 2; half++) {
                int row = m0 + wm + i * 16 + lr + half * 8;
                int col = n0 + wn + j * 8 + lc;
                float v0 = cv[half * 2 + 0];
                float v1 = cv[half * 2 + 1];
                size_t o = (size_t)row * N + col;
                if (epi == 1) {
                    float t0 = fast_gelu(v0 + bias[col]);
                    float t1 = fast_gelu(v1 + bias[col + 1]);
                    u16 h0, l0, h1, l1;
                    splitf(t0, h0, l0);
                    splitf(t1, h1, l1);
                    Ch[o] = h0; Cl[o] = l0;
                    Ch[o + 1] = h1; Cl[o + 1] = l1;
                } else if (epi == 3) {
                    Cf[o] = v0;
                    Cf[o + 1] = v1;
                } else {
                    if (bias) { v0 += bias[col]; v1 += (col + 1 < N) ? bias[col + 1] : 0.f; }
                    if (col < N) Cf[o] = v0;
                    if (col + 1 < N) Cf[o + 1] = v1;
                }
            }
        }
}

// ---------------------------------------------------------------------------
// Embedding
// ---------------------------------------------------------------------------
__global__ void embed_kernel(const float* __restrict__ states,
                             const int* __restrict__ actions,
                             const float* __restrict__ rtgs,
                             const int* __restrict__ tsteps,
                             const float* __restrict__ se_w, const float* __restrict__ se_b,
                             const float* __restrict__ re_w, const float* __restrict__ re_b,
                             const float* __restrict__ ae,
                             const float* __restrict__ pe,
                             const float* __restrict__ gpe) {
    int s = blockIdx.x;
    int b = blockIdx.y;
    int t = s / 3, kind = s % 3;
    int ts = tsteps[b];
    const float* g = gpe + (size_t)ts * DD;
    const float* p = pe + (size_t)s * DD;
    float* out = g_x + ((size_t)(b * SS + s)) * DD;

    if (kind == 0) {
        float r = rtgs[b * TT + t];
        for (int d = threadIdx.x; d < DD; d += blockDim.x)
            out[d] = fmaf(r, re_w[d], re_b[d]) + g[d] + p[d];
    } else if (kind == 1) {
        float st = states[b * TT + t];
        for (int d = threadIdx.x; d < DD; d += blockDim.x)
            out[d] = fmaf(st, se_w[d], se_b[d]) + g[d] + p[d];
    } else {
        int a = actions[b * TT + t];
        const float* av = ae + (size_t)a * DD;
        for (int d = threadIdx.x; d < DD; d += blockDim.x)
            out[d] = av[d] + g[d] + p[d];
    }
}

// ---------------------------------------------------------------------------
// LayerNorm (f32 in -> fp16 hi/lo out)
// ---------------------------------------------------------------------------
__global__ void __launch_bounds__(256) ln_kernel(const float* __restrict__ x,
                                                 const float* __restrict__ w,
                                                 const float* __restrict__ b,
                                                 u16* __restrict__ oh,
                                                 u16* __restrict__ ol) {
    int row = blockIdx.x;
    const float* xr = x + (size_t)row * DD;
    float v[4];
    float s = 0.f, s2 = 0.f;
#pragma unroll
    for (int i = 0; i < 4; i++) {
        float val = xr[threadIdx.x + i * 256];
        v[i] = val; s += val; s2 += val * val;
    }
#pragma unroll
    for (int o = 16; o; o >>= 1) {
        s  += __shfl_xor_sync(0xffffffffu, s,  o);
        s2 += __shfl_xor_sync(0xffffffffu, s2, o);
    }
    __shared__ float rs[8], rs2[8];
    int warp = threadIdx.x >> 5, lane = threadIdx.x & 31;
    if (!lane) { rs[warp] = s; rs2[warp] = s2; }
    __syncthreads();
    if (threadIdx.x == 0) {
        float a = 0.f, a2 = 0.f;
#pragma unroll
        for (int i = 0; i < 8; i++) { a += rs[i]; a2 += rs2[i]; }
        rs[0] = a; rs2[0] = a2;
    }
    __syncthreads();
    float mean = rs[0] * (1.f / DD);
    float var  = rs2[0] * (1.f / DD) - mean * mean;
    float inv  = rsqrtf(var + 1e-5f);
#pragma unroll
    for (int i = 0; i < 4; i++) {
        int d = threadIdx.x + i * 256;
        float t = (v[i] - mean) * inv * w[d] + b[d];
        u16 hi, lo;
        splitf(t, hi, lo);
        oh[(size_t)row * DD + d] = hi;
        ol[(size_t)row * DD + d] = lo;
    }
}

// Final LN with state-row gather
__global__ void __launch_bounds__(256) lnf_kernel(const float* __restrict__ w,
                                                  const float* __restrict__ b) {
    int m = blockIdx.x;
    int bb = m / TT, t = m % TT;
    int src = bb * SS + 3 * t + 1;
    const float* xr = g_x + (size_t)src * DD;
    float v[4];
    float s = 0.f, s2 = 0.f;
#pragma unroll
    for (int i = 0; i < 4; i++) {
        float val = xr[threadIdx.x + i * 256];
        v[i] = val; s += val; s2 += val * val;
    }
#pragma unroll
    for (int o = 16; o; o >>= 1) {
        s  += __shfl_xor_sync(0xffffffffu, s,  o);
        s2 += __shfl_xor_sync(0xffffffffu, s2, o);
    }
    __shared__ float rs[8], rs2[8];
    int warp = threadIdx.x >> 5, lane = threadIdx.x & 31;
    if (!lane) { rs[warp] = s; rs2[warp] = s2; }
    __syncthreads();
    if (threadIdx.x == 0) {
        float a = 0.f, a2 = 0.f;
#pragma unroll
        for (int i = 0; i < 8; i++) { a += rs[i]; a2 += rs2[i]; }
        rs[0] = a; rs2[0] = a2;
    }
    __syncthreads();
    float mean = rs[0] * (1.f / DD);
    float var  = rs2[0] * (1.f / DD) - mean * mean;
    float inv  = rsqrtf(var + 1e-5f);
#pragma unroll
    for (int i = 0; i < 4; i++) {
        int d = threadIdx.x + i * 256;
        float t2 = (v[i] - mean) * inv * w[d] + b[d];
        u16 hi, lo;
        splitf(t2, hi, lo);
        g_h_hi[(size_t)m * DD + d] = hi;
        g_h_lo[(size_t)m * DD + d] = lo;
    }
}

// ---------------------------------------------------------------------------
// Flash attention (f32 compute, fp16 hi/lo output)
// ---------------------------------------------------------------------------
__global__ void __launch_bounds__(128) attn_flash() {
    extern __shared__ float sm[];
    float* Qs = sm;
    float* Ks = sm + 64 * QS;
    float* Ps = sm + 2 * 64 * QS;
    float* Vs = sm + 3 * 64 * QS;

    const int qt = blockIdx.x, h = blockIdx.y, b = blockIdx.z;
    const float* base = g_qkv + (size_t)b * SS * (3 * DD);
    const int tid = threadIdx.x;
    const int tq = tid >> 3, tk = tid & 7;

    for (int i = tid; i < 1024; i += 128) {
        int r = i >> 4, dg = i & 15;
        float4 v = *reinterpret_cast<const float4*>(
            &base[(size_t)(qt * 64 + r) * (3 * DD) + h * HDIM + dg * 4]);
        Qs[(dg * 4 + 0) * QS + r] = v.x;
        Qs[(dg * 4 + 1) * QS + r] = v.y;
        Qs[(dg * 4 + 2) * QS + r] = v.z;
        Qs[(dg * 4 + 3) * QS + r] = v.w;
    }

    float m_i[4], l_i[4], O[4][8];
#pragma unroll
    for (int i = 0; i < 4; i++) {
        m_i[i] = -1e30f; l_i[i] = 0.f;
#pragma unroll
        for (int j = 0; j < 8; j++) O[i][j] = 0.f;
    }

    for (int kt = 0; kt <= qt; kt++) {
        __syncthreads();
        for (int i = tid; i < 1024; i += 128) {
            int r = i >> 4, dg = i & 15;
            const float* krow = &base[(size_t)(kt * 64 + r) * (3 * DD) + DD + h * HDIM];
            float4 kv = *reinterpret_cast<const float4*>(krow + dg * 4);
            Ks[(dg * 4 + 0) * QS + r] = kv.x;
            Ks[(dg * 4 + 1) * QS + r] = kv.y;
            Ks[(dg * 4 + 2) * QS + r] = kv.z;
            Ks[(dg * 4 + 3) * QS + r] = kv.w;
            float4 vv = *reinterpret_cast<const float4*>(
                &base[(size_t)(kt * 64 + r) * (3 * DD) + 2 * DD + h * HDIM + dg * 4]);
            *reinterpret_cast<float4*>(&Vs[r * 64 + dg * 4]) = vv;
        }
        __syncthreads();

        float s[4][8];
#pragma unroll
        for (int i = 0; i < 4; i++)
#pragma unroll
            for (int j = 0; j < 8; j++) s[i][j] = 0.f;
#pragma unroll 8
        for (int d = 0; d < 64; d++) {
            float4 a = *reinterpret_cast<const float4*>(&Qs[d * QS + tq * 4]);
            float4 b0 = *reinterpret_cast<const float4*>(&Ks[d * QS + tk * 8]);
            float4 b1 = *reinterpret_cast<const float4*>(&Ks[d * QS + tk * 8 + 4]);
            float ar[4] = {a.x, a.y, a.z, a.w};
            float br[8] = {b0.x, b0.y, b0.z, b0.w, b1.x, b1.y, b1.z, b1.w};
#pragma unroll
            for (int i = 0; i < 4; i++)
#pragma unroll
                for (int j = 0; j < 8; j++)
                    s[i][j] = fmaf(ar[i], br[j], s[i][j]);
        }
        const bool diag = (kt == qt);
#pragma unroll
        for (int i = 0; i < 4; i++) {
            int qg = qt * 64 + tq * 4 + i;
#pragma unroll
            for (int j = 0; j < 8; j++) {
                int kg = kt * 64 + tk * 8 + j;
                s[i][j] = (diag && kg > qg) ? -1e30f : s[i][j] * 0.125f;
            }
        }
        float e[4][8];
#pragma unroll
        for (int i = 0; i < 4; i++) {
            float rm = s[i][0];
#pragma unroll
            for (int j = 1; j < 8; j++) rm = fmaxf(rm, s[i][j]);
            rm = fmaxf(rm, __shfl_xor_sync(0xffffffffu, rm, 1));
            rm = fmaxf(rm, __shfl_xor_sync(0xffffffffu, rm, 2));
            rm = fmaxf(rm, __shfl_xor_sync(0xffffffffu, rm, 4));
            float newm = fmaxf(m_i[i], rm);
            float f = __expf(m_i[i] - newm);
            float es = 0.f;
#pragma unroll
            for (int j = 0; j < 8; j++) {
                float ev = __expf(s[i][j] - newm);
                e[i][j] = ev; es += ev;
            }
            es += __shfl_xor_sync(0xffffffffu, es, 1);
            es += __shfl_xor_sync(0xffffffffu, es, 2);
            es += __shfl_xor_sync(0xffffffffu, es, 4);
            l_i[i] = l_i[i] * f + es;
            m_i[i] = newm;
#pragma unroll
            for (int j = 0; j < 8; j++) O[i][j] *= f;
        }
#pragma unroll
        for (int j = 0; j < 8; j++)
#pragma unroll
            for (int i = 0; i < 4; i++)
                Ps[(tk * 8 + j) * QS + tq * 4 + i] = e[i][j];
        __syncthreads();
#pragma unroll 8
        for (int k = 0; k < 64; k++) {
            float4 a = *reinterpret_cast<const float4*>(&Ps[k * QS + tq * 4]);
            float4 b0 = *reinterpret_cast<const float4*>(&Vs[k * 64 + tk * 8]);
            float4 b1 = *reinterpret_cast<const float4*>(&Vs[k * 64 + tk * 8 + 4]);
            float ar[4] = {a.x, a.y, a.z, a.w};
            float br[8] = {b0.x, b0.y, b0.z, b0.w, b1.x, b1.y, b1.z, b1.w};
#pragma unroll
            for (int i = 0; i < 4; i++)
#pragma unroll
                for (int j = 0; j < 8; j++)
                    O[i][j] = fmaf(ar[i], br[j], O[i][j]);
        }
    }

#pragma unroll
    for (int i = 0; i < 4; i++) {
        float inv = 1.f / l_i[i];
        int q = qt * 64 + tq * 4 + i;
        size_t o = ((size_t)(b * SS + q)) * DD + h * HDIM + tk * 8;
#pragma unroll
        for (int j = 0; j < 8; j++) {
            u16 hi, lo;
            splitf(O[i][j] * inv, hi, lo);
            g_y_hi[o + j] = hi;
            g_y_lo[o + j] = lo;
        }
    }
}

// ---------------------------------------------------------------------------
// Launcher
// ---------------------------------------------------------------------------
extern "C" void kernel_launch(void* const* d_in, const int* in_sizes, int n_in,
                              void* d_out, int out_size) {
    const float* states  = (const float*)d_in[0];
    const int*   actions = (const int*)  d_in[1];
    const float* rtgs    = (const float*)d_in[2];
    const int*   tsteps  = (const int*)  d_in[3];
    const float* se_w = (const float*)d_in[4],  *se_b = (const float*)d_in[5];
    const float* re_w = (const float*)d_in[6],  *re_b = (const float*)d_in[7];
    const float* ae   = (const float*)d_in[8];
    const float* pe   = (const float*)d_in[9];
    const float* gpe  = (const float*)d_in[10];
    const float* ln1_w = (const float*)d_in[11], *ln1_b = (const float*)d_in[12];
    const float* qkv_w = (const float*)d_in[13], *qkv_b = (const float*)d_in[14];
    const float* proj_w= (const float*)d_in[15], *proj_b= (const float*)d_in[16];
    const float* ln2_w = (const float*)d_in[17], *ln2_b = (const float*)d_in[18];
    const float* fc_w  = (const float*)d_in[19], *fc_b  = (const float*)d_in[20];
    const float* fcp_w = (const float*)d_in[21], *fcp_b = (const float*)d_in[22];
    const float* lnf_w = (const float*)d_in[23], *lnf_b = (const float*)d_in[24];
    const float* lm_w  = (const float*)d_in[25];
    float* out = (float*)d_out;

    float *x, *qkv, *part;
    u16 *hh, *hl, *yh, *yl, *ffh, *ffl;
    u16 *wqh, *wql, *wph, *wpl, *wfh, *wfl, *wgh, *wgl, *wlh, *wll;
    cudaGetSymbolAddress((void**)&x,    g_x);
    cudaGetSymbolAddress((void**)&qkv,  g_qkv);
    cudaGetSymbolAddress((void**)&part, g_part);
    cudaGetSymbolAddress((void**)&hh,   g_h_hi);
    cudaGetSymbolAddress((void**)&hl,   g_h_lo);
    cudaGetSymbolAddress((void**)&yh,   g_y_hi);
    cudaGetSymbolAddress((void**)&yl,   g_y_lo);
    cudaGetSymbolAddress((void**)&ffh,  g_ff_hi);
    cudaGetSymbolAddress((void**)&ffl,  g_ff_lo);
    cudaGetSymbolAddress((void**)&wqh,  w_qkv_h);
    cudaGetSymbolAddress((void**)&wql,  w_qkv_l);
    cudaGetSymbolAddress((void**)&wph,  w_proj_h);
    cudaGetSymbolAddress((void**)&wpl,  w_proj_l);
    cudaGetSymbolAddress((void**)&wfh,  w_fc_h);
    cudaGetSymbolAddress((void**)&wfl,  w_fc_l);
    cudaGetSymbolAddress((void**)&wgh,  w_fcp_h);
    cudaGetSymbolAddress((void**)&wgl,  w_fcp_l);
    cudaGetSymbolAddress((void**)&wlh,  w_lm_h);
    cudaGetSymbolAddress((void**)&wll,  w_lm_l);

    const int SMEM_ATTN = (3 * 64 * QS + 64 * 64) * 4;   // 68608
    const int SMEM_GEMM = 2 * STAGE_U16 * 2;             // 81920
    cudaFuncSetAttribute(attn_flash,
                         cudaFuncAttributeMaxDynamicSharedMemorySize, SMEM_ATTN);
    cudaFuncSetAttribute(gemm_mma,
                         cudaFuncAttributeMaxDynamicSharedMemorySize, SMEM_GEMM);

    const int total4 = NR * DD / 4;
    const int cgrid = (total4 + 255) / 256;

    // Launch order: #4 is the layer-0 QKV GEMM (ncu profiles the 4th launch).
    wconv<<<dim3(3072 / 32, 1024 / 32, LL), dim3(32, 8)>>>(qkv_w, wqh, wql, 1024, 3072); // 1
    embed_kernel<<<dim3(SS, BB), 256>>>(states, actions, rtgs, tsteps,
                                        se_w, se_b, re_w, re_b, ae, pe, gpe);            // 2
    ln_kernel<<<NR, 256>>>(x, ln1_w, ln1_b, hh, hl);                                     // 3

    for (int l = 0; l < LL; l++) {
        gemm_mma<<<dim3(3072 / 128, NR / 128), 256, SMEM_GEMM>>>(                         // 4 on l=0
            hh, hl, wqh + (size_t)l * 3072 * 1024, wql + (size_t)l * 3072 * 1024,
            qkv_b + (size_t)l * 3072, qkv, nullptr, nullptr,
            3072, 1024, 1024, 0, 0);
        if (l == 0) {
            wconv<<<dim3(1024 / 32, 1024 / 32, LL), dim3(32, 8)>>>(proj_w, wph, wpl, 1024, 1024);
            wconv<<<dim3(4096 / 32, 1024 / 32, LL), dim3(32, 8)>>>(fc_w, wfh, wfl, 1024, 4096);
            wconv<<<dim3(1024 / 32, 4096 / 32, LL), dim3(32, 8)>>>(fcp_w, wgh, wgl, 4096, 1024);
            lmconv<<<(SZ_LM + 255) / 256, 256>>>(lm_w, wlh, wll, SZ_LM);
        }
        attn_flash<<<dim3(SS / 64, HH, BB), 128, SMEM_ATTN>>>();
        gemm_mma<<<dim3(1024 / 128, NR / 128, 4), 256, SMEM_GEMM>>>(
            yh, yl, wph + (size_t)l * 1024 * 1024, wpl + (size_t)l * 1024 * 1024,
            nullptr, part, nullptr, nullptr, 1024, 256, 1024, 3, 0);
        combine_ln<<<NR, 256>>>(part, proj_b + (size_t)l * 1024,
                                ln2_w + l * DD, ln2_b + l * DD, x, hh, hl);
        gemm_mma<<<dim3(4096 / 128, NR / 128), 256, SMEM_GEMM>>>(
            hh, hl, wfh + (size_t)l * 4096 * 1024, wfl + (size_t)l * 4096 * 1024,
            fc_b + (size_t)l * 4096, nullptr, ffh, ffl,
            4096, 1024, 1024, 1, 0);
        gemm_mma<<<dim3(1024 / 128, NR / 128, 4), 256, SMEM_GEMM>>>(
            ffh, ffl, wgh + (size_t)l * 1024 * 4096, wgl + (size_t)l * 1024 * 4096,
            nullptr, part, nullptr, nullptr, 1024, 1024, 4096, 3, 0);
        if (l < LL - 1) {
            combine_ln<<<NR, 256>>>(part, fcp_b + (size_t)l * 1024,
                                    ln1_w + (l + 1) * DD, ln1_b + (l + 1) * DD,
                                    x, hh, hl);
        } else {
            combine4<<<cgrid, 256>>>((const float4*)part, fcp_b + (size_t)l * 1024,
                                     (float4*)x, total4);
            lnf_kernel<<<BB * TT, 256>>>(lnf_w, lnf_b);
        }
    }

    gemm_mma<<<dim3((VV + 127) / 128, (BB * TT) / 128), 256, SMEM_GEMM>>>(
        hh, hl, wlh, wll, nullptr, out, nullptr, nullptr,
        VV, 1024, 1024, 0, 1);
}